// round 12
// baseline (speedup 1.0000x reference)
#include <cuda_runtime.h>
#include <cuda_bf16.h>
#include <math.h>
#include <cstdint>

// Problem constants
#define BB 4
#define NN 1024
#define DD 1024
#define HH 16
#define DHH 64
#define INNERC 1024          // HH*DHH
#define QKVC 3072            // 3*INNERC
#define MM 4096              // BB*NN
#define BHC 64               // BB*HH

// ---------------------------------------------------------------------------
// Scratch (__device__ globals; no allocation allowed)
// ---------------------------------------------------------------------------
// int8 quantized operands (q = 256*h + l, value = s * q)
__device__ int8_t g_xh8[(size_t)MM * DD];
__device__ int8_t g_xl8[(size_t)MM * DD];
__device__ float  g_sx[MM];
__device__ int8_t g_wqh8[(size_t)QKVC * DD];     // w_qkv^T quantized
__device__ int8_t g_wql8[(size_t)QKVC * DD];
__device__ unsigned g_tmq[QKVC];                 // col-max of w_qkv (as uint)
__device__ int8_t g_woh8[(size_t)INNERC * INNERC];
__device__ int8_t g_wol8[(size_t)INNERC * INNERC];
__device__ unsigned g_tmo[INNERC];
__device__ int8_t g_aoh8[(size_t)MM * INNERC];
__device__ int8_t g_aol8[(size_t)MM * INNERC];
__device__ float  g_sao[MM];

// q/k in [B,H,N,DH] bf16 hi/lo (q pre-scaled by 0.125)
__device__ __nv_bfloat16 g_qhi[(size_t)BHC * NN * DHH];
__device__ __nv_bfloat16 g_qlo[(size_t)BHC * NN * DHH];
__device__ __nv_bfloat16 g_khi[(size_t)BHC * NN * DHH];
__device__ __nv_bfloat16 g_klo[(size_t)BHC * NN * DHH];
// v stored directly transposed: [B,H,DH,N]
__device__ __nv_bfloat16 g_vThi[(size_t)BHC * DHH * NN];
__device__ __nv_bfloat16 g_vTlo[(size_t)BHC * DHH * NN];
// attention output fp32 [B*N, INNER]
__device__ float g_ao[(size_t)MM * INNERC];

// ---------------------------------------------------------------------------
// PTX helpers (sm_80-compatible; compile on plain compute_103)
// ---------------------------------------------------------------------------
__device__ __forceinline__ uint32_t smem_u32(const void* p) {
    uint32_t a;
    asm("{ .reg .u64 t; cvta.to.shared.u64 t, %1; cvt.u32.u64 %0, t; }"
        : "=r"(a) : "l"(p));
    return a;
}
#define LDSM4(r, addr) \
    asm volatile("ldmatrix.sync.aligned.m8n8.x4.shared.b16 {%0,%1,%2,%3}, [%4];" \
        : "=r"((r)[0]), "=r"((r)[1]), "=r"((r)[2]), "=r"((r)[3]) : "r"(addr))
#define MMA_BF16(d, a, b) \
    asm volatile("mma.sync.aligned.m16n8k16.row.col.f32.bf16.bf16.f32 " \
        "{%0,%1,%2,%3}, {%4,%5,%6,%7}, {%8,%9}, {%0,%1,%2,%3};" \
        : "+f"((d)[0]), "+f"((d)[1]), "+f"((d)[2]), "+f"((d)[3]) \
        : "r"((a)[0]), "r"((a)[1]), "r"((a)[2]), "r"((a)[3]), \
          "r"((b)[0]), "r"((b)[1]))
#define MMA_S8(d, a, b) \
    asm volatile("mma.sync.aligned.m16n8k32.row.col.s32.s8.s8.s32 " \
        "{%0,%1,%2,%3}, {%4,%5,%6,%7}, {%8,%9}, {%0,%1,%2,%3};" \
        : "+r"((d)[0]), "+r"((d)[1]), "+r"((d)[2]), "+r"((d)[3]) \
        : "r"((a)[0]), "r"((a)[1]), "r"((a)[2]), "r"((a)[3]), \
          "r"((b)[0]), "r"((b)[1]))
#define CP16(saddr, g) \
    asm volatile("cp.async.cg.shared.global [%0], [%1], 16;" :: "r"(saddr), "l"(g))
#define CP_COMMIT() asm volatile("cp.async.commit_group;" ::: "memory")
#define CP_WAIT0()  asm volatile("cp.async.wait_group 0;" ::: "memory")

__device__ __forceinline__ void store_hilo2(
    __nv_bfloat16* hb, __nv_bfloat16* lb, size_t idx, float a, float b)
{
    __nv_bfloat16 h0 = __float2bfloat16(a);
    __nv_bfloat16 h1 = __float2bfloat16(b);
    *(__nv_bfloat162*)(hb + idx) = __nv_bfloat162(h0, h1);
    *(__nv_bfloat162*)(lb + idx) =
        __nv_bfloat162(__float2bfloat16(a - __bfloat162float(h0)),
                       __float2bfloat16(b - __bfloat162float(h1)));
}
__device__ __forceinline__ void store_hilo1(
    __nv_bfloat16* hb, __nv_bfloat16* lb, size_t idx, float a)
{
    __nv_bfloat16 h0 = __float2bfloat16(a);
    hb[idx] = h0;
    lb[idx] = __float2bfloat16(a - __bfloat162float(h0));
}
__device__ __forceinline__ void cvt_hilo(float a, float b, uint32_t& h, uint32_t& l)
{
    __nv_bfloat16 ha = __float2bfloat16(a);
    __nv_bfloat16 hbb = __float2bfloat16(b);
    __nv_bfloat162 hp(ha, hbb);
    h = *(uint32_t*)&hp;
    __nv_bfloat162 lp(__float2bfloat16(a - __bfloat162float(ha)),
                      __float2bfloat16(b - __bfloat162float(hbb)));
    l = *(uint32_t*)&lp;
}
__device__ __forceinline__ void quant1(float v, float inv, int8_t& h, int8_t& l)
{
    int qi = __float2int_rn(v * inv);
    int hi = (qi + 128) >> 8;
    int li = qi - (hi << 8);
    h = (int8_t)hi; l = (int8_t)li;
}

// ---------------------------------------------------------------------------
// quant prep kernels
// ---------------------------------------------------------------------------
// per-row quantization of a [R,1024] fp32 matrix
__global__ void __launch_bounds__(256) rowquant1024(
    const float* __restrict__ in, int8_t* __restrict__ h8,
    int8_t* __restrict__ l8, float* __restrict__ s)
{
    const int row = blockIdx.x;
    const int tid = threadIdx.x;
    const float4 v = *(const float4*)(in + (size_t)row * 1024 + tid * 4);
    __shared__ float red[256];
    float mx = fmaxf(fmaxf(fabsf(v.x), fabsf(v.y)), fmaxf(fabsf(v.z), fabsf(v.w)));
    red[tid] = mx;
    __syncthreads();
#pragma unroll
    for (int st = 128; st > 0; st >>= 1) {
        if (tid < st) red[tid] = fmaxf(red[tid], red[tid + st]);
        __syncthreads();
    }
    mx = red[0];
    const float inv = (mx > 0.f) ? 32512.f / mx : 0.f;
    if (tid == 0) s[row] = mx * (1.f / 32512.f);
    int8_t h0, h1, h2, h3, l0, l1, l2, l3;
    quant1(v.x, inv, h0, l0); quant1(v.y, inv, h1, l1);
    quant1(v.z, inv, h2, l2); quant1(v.w, inv, h3, l3);
    *(char4*)(h8 + (size_t)row * 1024 + tid * 4) = make_char4(h0, h1, h2, h3);
    *(char4*)(l8 + (size_t)row * 1024 + tid * 4) = make_char4(l0, l1, l2, l3);
}

// column abs-max of fp32 [R,C] via atomicMax on uint (floats >= 0)
__global__ void __launch_bounds__(256) colmax_kernel(
    const float* __restrict__ w, unsigned* __restrict__ tm, int R, int C)
{
    const int j = blockIdx.x * 256 + threadIdx.x;
    const int chunk = R >> 3;
    const int r0 = blockIdx.y * chunk;
    float mx = 0.f;
    for (int r = r0; r < r0 + chunk; ++r)
        mx = fmaxf(mx, fabsf(w[(size_t)r * C + j]));
    atomicMax(&tm[j], __float_as_uint(mx));
}

// transpose + quantize: fp32 w[R,C] -> int8 hT/lT [C,R] with col scales tm
__global__ void __launch_bounds__(256) quantT_kernel(
    const float* __restrict__ w, const unsigned* __restrict__ tm,
    int8_t* __restrict__ hT, int8_t* __restrict__ lT, int R, int C)
{
    __shared__ float t[32][33];
    const int c = blockIdx.x * 32 + threadIdx.x;
#pragma unroll
    for (int j = 0; j < 4; ++j) {
        int r = blockIdx.y * 32 + threadIdx.y + j * 8;
        t[threadIdx.y + j * 8][threadIdx.x] = w[(size_t)r * C + c];
    }
    __syncthreads();
    const int rr = blockIdx.y * 32 + threadIdx.x;
#pragma unroll
    for (int j = 0; j < 4; ++j) {
        int cc = blockIdx.x * 32 + threadIdx.y + j * 8;
        const float mx = __uint_as_float(tm[cc]);
        const float inv = (mx > 0.f) ? 32512.f / mx : 0.f;
        int8_t h, l;
        quant1(t[threadIdx.x][threadIdx.y + j * 8], inv, h, l);
        hT[(size_t)cc * R + rr] = h;
        lT[(size_t)cc * R + rr] = l;
    }
}

// ---------------------------------------------------------------------------
// int8 GEMM tiling: 128x128 CTA tile, BK=64 (bytes), 16 warps 32x32, 2-stage
// ---------------------------------------------------------------------------
#define I8STRIDE 80                          // 64 data + 16 pad bytes per row
#define I8TILEB (128 * I8STRIDE)             // 10240
#define I8STAGEB (4 * I8TILEB)               // 40960
#define I8_SMEM_BYTES (2 * I8STAGEB)         // 81920

// common int8 mainloop producing acch/accm for a 128x128 tile
#define I8_GEMM_BODY(Ah8, Al8, Bh8, Bl8, Kdim)                                \
    const int grow = tid >> 2;                                                \
    const int gcol = (tid & 3) << 4;                                          \
    const int8_t* gAh = (Ah8) + (size_t)(m0 + grow) * (Kdim) + gcol;          \
    const int8_t* gAl = (Al8) + (size_t)(m0 + grow) * (Kdim) + gcol;          \
    const int8_t* gBh = (Bh8) + (size_t)(n0 + grow) * (Kdim) + gcol;          \
    const int8_t* gBl = (Bl8) + (size_t)(n0 + grow) * (Kdim) + gcol;          \
    const uint32_t stb = (uint32_t)(grow * I8STRIDE + gcol);                  \
    uint32_t aoff[2];                                                         \
    _Pragma("unroll")                                                         \
    for (int mt = 0; mt < 2; ++mt)                                            \
        aoff[mt] = (uint32_t)((mw * 32 + mt * 16 + (lane & 15)) * I8STRIDE    \
                              + ((lane >> 4) << 4));                          \
    const int brow = nw * 32 + (lane & 7) + ((lane >> 4) << 3);               \
    const int bcol = ((lane >> 3) & 1) << 4;                                  \
    uint32_t boff[2];                                                         \
    boff[0] = (uint32_t)(brow * I8STRIDE + bcol);                             \
    boff[1] = (uint32_t)((brow + 16) * I8STRIDE + bcol);                      \
    int acch[2][4][4], accm[2][4][4];                                         \
    _Pragma("unroll")                                                         \
    for (int i = 0; i < 2; ++i)                                               \
        _Pragma("unroll")                                                     \
        for (int j = 0; j < 4; ++j)                                           \
            _Pragma("unroll")                                                 \
            for (int k = 0; k < 4; ++k) { acch[i][j][k] = 0; accm[i][j][k] = 0; } \
    const int nst = (Kdim) >> 6;                                              \
    {                                                                         \
        const uint32_t d = smb + stb;                                         \
        CP16(d,               gAh);                                           \
        CP16(d + I8TILEB,     gAl);                                           \
        CP16(d + 2 * I8TILEB, gBh);                                           \
        CP16(d + 3 * I8TILEB, gBl);                                           \
        CP_COMMIT(); CP_WAIT0();                                              \
    }                                                                         \
    __syncthreads();                                                          \
    for (int s = 0; s < nst; ++s) {                                           \
        if (s + 1 < nst) {                                                    \
            const int k0 = (s + 1) << 6;                                      \
            const uint32_t d = smb + ((s + 1) & 1) * I8STAGEB + stb;          \
            CP16(d,               gAh + k0);                                  \
            CP16(d + I8TILEB,     gAl + k0);                                  \
            CP16(d + 2 * I8TILEB, gBh + k0);                                  \
            CP16(d + 3 * I8TILEB, gBl + k0);                                  \
            CP_COMMIT();                                                      \
        }                                                                     \
        const uint32_t sb = smb + (s & 1) * I8STAGEB;                         \
        _Pragma("unroll")                                                     \
        for (int kk = 0; kk < 2; ++kk) {                                      \
            const uint32_t kb = kk * 32;                                      \
            uint32_t ah[2][4], al[2][4], bh[4][2], bl[4][2];                  \
            _Pragma("unroll")                                                 \
            for (int mt = 0; mt < 2; ++mt) {                                  \
                LDSM4(ah[mt], sb + aoff[mt] + kb);                            \
                LDSM4(al[mt], sb + I8TILEB + aoff[mt] + kb);                  \
            }                                                                 \
            _Pragma("unroll")                                                 \
            for (int p = 0; p < 2; ++p) {                                     \
                uint32_t t4[4];                                               \
                LDSM4(t4, sb + 2 * I8TILEB + boff[p] + kb);                   \
                bh[2 * p][0] = t4[0]; bh[2 * p][1] = t4[1];                   \
                bh[2 * p + 1][0] = t4[2]; bh[2 * p + 1][1] = t4[3];           \
                LDSM4(t4, sb + 3 * I8TILEB + boff[p] + kb);                   \
                bl[2 * p][0] = t4[0]; bl[2 * p][1] = t4[1];                   \
                bl[2 * p + 1][0] = t4[2]; bl[2 * p + 1][1] = t4[3];           \
            }                                                                 \
            _Pragma("unroll")                                                 \
            for (int mt = 0; mt < 2; ++mt)                                    \
                _Pragma("unroll")                                             \
                for (int nt = 0; nt < 4; ++nt)                                \
                    MMA_S8(acch[mt][nt], ah[mt], bh[nt]);                     \
            _Pragma("unroll")                                                 \
            for (int mt = 0; mt < 2; ++mt)                                    \
                _Pragma("unroll")                                             \
                for (int nt = 0; nt < 4; ++nt)                                \
                    MMA_S8(accm[mt][nt], ah[mt], bl[nt]);                     \
            _Pragma("unroll")                                                 \
            for (int mt = 0; mt < 2; ++mt)                                    \
                _Pragma("unroll")                                             \
                for (int nt = 0; nt < 4; ++nt)                                \
                    MMA_S8(accm[mt][nt], al[mt], bh[nt]);                     \
        }                                                                     \
        CP_WAIT0();                                                           \
        __syncthreads();                                                      \
    }

// dequant: value = s_a * t_b * (65536*hh + 256*mid)
__device__ __forceinline__ float deq(int hh, int mid, float sa, float tb)
{
    return (65536.f * (float)hh + 256.f * (float)mid) * sa * tb;
}

// ---------------------------------------------------------------------------
// qkv GEMM (int8): writes q(*0.125)/k bf16 hi/lo [B,H,N,DH], v -> [B,H,DH,N]
// ---------------------------------------------------------------------------
__global__ void __launch_bounds__(512, 1) gemm_qkv_i8(
    const int8_t* __restrict__ Ah8, const int8_t* __restrict__ Al8,
    const float* __restrict__ sA,
    const int8_t* __restrict__ Bh8, const int8_t* __restrict__ Bl8,
    const unsigned* __restrict__ tmB,
    __nv_bfloat16* __restrict__ qhi, __nv_bfloat16* __restrict__ qlo,
    __nv_bfloat16* __restrict__ khi, __nv_bfloat16* __restrict__ klo,
    __nv_bfloat16* __restrict__ vThi, __nv_bfloat16* __restrict__ vTlo)
{
    extern __shared__ char smem[];
    const uint32_t smb = smem_u32(smem);
    const int tid = threadIdx.x;
    const int lane = tid & 31;
    const int wid = tid >> 5;
    const int mw = wid >> 2;
    const int nw = wid & 3;
    const int m0 = blockIdx.y * 128;
    const int n0 = blockIdx.x * 128;

    I8_GEMM_BODY(Ah8, Al8, Bh8, Bl8, DD)

    // epilogue
#pragma unroll
    for (int nt = 0; nt < 4; ++nt) {
        const int cc = n0 + nw * 32 + nt * 8 + ((lane & 3) << 1);
        const float t0 = __uint_as_float(tmB[cc])     * (1.f / 32512.f);
        const float t1 = __uint_as_float(tmB[cc + 1]) * (1.f / 32512.f);
        const int sec = cc >> 10;
        const int h = (cc & 1023) >> 6;
        const int d = cc & 63;
#pragma unroll
        for (int mt = 0; mt < 2; ++mt) {
            const int r0 = m0 + mw * 32 + mt * 16 + (lane >> 2);
            const float sa0 = sA[r0];
            const float sa1 = sA[r0 + 8];
            const float v00 = deq(acch[mt][nt][0], accm[mt][nt][0], sa0, t0);
            const float v01 = deq(acch[mt][nt][1], accm[mt][nt][1], sa0, t1);
            const float v10 = deq(acch[mt][nt][2], accm[mt][nt][2], sa1, t0);
            const float v11 = deq(acch[mt][nt][3], accm[mt][nt][3], sa1, t1);
            const int b = r0 >> 10;
            const int n = r0 & 1023;
            const size_t bhbase = ((size_t)b * HH + h);
            if (sec == 0) {
                store_hilo2(qhi, qlo, (bhbase * NN + n) * DHH + d,
                            v00 * 0.125f, v01 * 0.125f);
                store_hilo2(qhi, qlo, (bhbase * NN + n + 8) * DHH + d,
                            v10 * 0.125f, v11 * 0.125f);
            } else if (sec == 1) {
                store_hilo2(khi, klo, (bhbase * NN + n) * DHH + d, v00, v01);
                store_hilo2(khi, klo, (bhbase * NN + n + 8) * DHH + d, v10, v11);
            } else {
                const size_t vb = bhbase * DHH;
                store_hilo1(vThi, vTlo, (vb + d) * NN + n,         v00);
                store_hilo1(vThi, vTlo, (vb + d + 1) * NN + n,     v01);
                store_hilo1(vThi, vTlo, (vb + d) * NN + n + 8,     v10);
                store_hilo1(vThi, vTlo, (vb + d + 1) * NN + n + 8, v11);
            }
        }
    }
}

// ---------------------------------------------------------------------------
// out-projection GEMM (int8): fp32 out + bias
// ---------------------------------------------------------------------------
__global__ void __launch_bounds__(512, 1) gemm_out_i8(
    const int8_t* __restrict__ Ah8, const int8_t* __restrict__ Al8,
    const float* __restrict__ sA,
    const int8_t* __restrict__ Bh8, const int8_t* __restrict__ Bl8,
    const unsigned* __restrict__ tmB,
    const float* __restrict__ bias, float* __restrict__ C, int Ncols)
{
    extern __shared__ char smem[];
    const uint32_t smb = smem_u32(smem);
    const int tid = threadIdx.x;
    const int lane = tid & 31;
    const int wid = tid >> 5;
    const int mw = wid >> 2;
    const int nw = wid & 3;
    const int m0 = blockIdx.y * 128;
    const int n0 = blockIdx.x * 128;

    I8_GEMM_BODY(Ah8, Al8, Bh8, Bl8, INNERC)

#pragma unroll
    for (int mt = 0; mt < 2; ++mt) {
        const int r0 = m0 + mw * 32 + mt * 16 + (lane >> 2);
        const float sa0 = sA[r0];
        const float sa1 = sA[r0 + 8];
#pragma unroll
        for (int nt = 0; nt < 4; ++nt) {
            const int cc = n0 + nw * 32 + nt * 8 + ((lane & 3) << 1);
            const float t0 = __uint_as_float(tmB[cc])     * (1.f / 32512.f);
            const float t1 = __uint_as_float(tmB[cc + 1]) * (1.f / 32512.f);
            const float2 bv = *(const float2*)(bias + cc);
            float2 v0, v1;
            v0.x = deq(acch[mt][nt][0], accm[mt][nt][0], sa0, t0) + bv.x;
            v0.y = deq(acch[mt][nt][1], accm[mt][nt][1], sa0, t1) + bv.y;
            v1.x = deq(acch[mt][nt][2], accm[mt][nt][2], sa1, t0) + bv.x;
            v1.y = deq(acch[mt][nt][3], accm[mt][nt][3], sa1, t1) + bv.y;
            *(float2*)(C + (size_t)r0 * Ncols + cc) = v0;
            *(float2*)(C + (size_t)(r0 + 8) * Ncols + cc) = v1;
        }
    }
}

// ---------------------------------------------------------------------------
// flash_tc: fused masked attention per (bh, 128-row Q tile); fp32 ao out.
// ---------------------------------------------------------------------------
#define FQSTR 72
#define FQTILE 18432                      // 128*72*2
#define FVSTR 136
#define FVTILE 17408                      // 64*136*2
#define F_MASK 0
#define F_QHI 4096
#define F_QLO (F_QHI + FQTILE)
#define F_K(st) (40960 + (st) * 2 * FQTILE)
#define F_V(st) (114688 + (st) * 2 * FVTILE)
#define FLASH_SMEM 184320

__global__ void __launch_bounds__(256, 1) flash_tc(
    const __nv_bfloat16* __restrict__ qhi, const __nv_bfloat16* __restrict__ qlo,
    const __nv_bfloat16* __restrict__ khi, const __nv_bfloat16* __restrict__ klo,
    const __nv_bfloat16* __restrict__ vThi, const __nv_bfloat16* __restrict__ vTlo,
    const float* __restrict__ mask, float* __restrict__ ao)
{
    extern __shared__ char smem[];
    const uint32_t smb = smem_u32(smem);
    const int tid = threadIdx.x;
    const int lane = tid & 31;
    const int wid = tid >> 5;
    const int bh = blockIdx.y;
    const int b = bh >> 4;
    const int h = bh & 15;
    const int i0 = blockIdx.x * 128;
    const size_t hb = (size_t)bh * NN * DHH;

    const __nv_bfloat16* kH = khi + hb;
    const __nv_bfloat16* kL = klo + hb;
    const __nv_bfloat16* vH = vThi + (size_t)bh * DHH * NN;
    const __nv_bfloat16* vL = vTlo + (size_t)bh * DHH * NN;

    CP16(smb + F_MASK + tid * 16, mask + b * NN + tid * 4);
#pragma unroll
    for (int t = 0; t < 4; ++t) {
        const int idx = tid + t * 256;
        const int row = idx >> 3;
        const int col = (idx & 7) << 3;
        const uint32_t so = (uint32_t)(row * FQSTR + col) * 2;
        CP16(smb + F_QHI + so, qhi + hb + (size_t)(i0 + row) * DHH + col);
        CP16(smb + F_QLO + so, qlo + hb + (size_t)(i0 + row) * DHH + col);
        CP16(smb + F_K(0) + so,          kH + (size_t)row * DHH + col);
        CP16(smb + F_K(0) + FQTILE + so, kL + (size_t)row * DHH + col);
    }
#pragma unroll
    for (int t = 0; t < 4; ++t) {
        const int idx = tid + t * 256;
        const int vr = idx >> 4;
        const int vc = (idx & 15) << 3;
        const uint32_t so = (uint32_t)(vr * FVSTR + vc) * 2;
        CP16(smb + F_V(0) + so,          vH + (size_t)vr * NN + vc);
        CP16(smb + F_V(0) + FVTILE + so, vL + (size_t)vr * NN + vc);
    }
    CP_COMMIT(); CP_WAIT0();
    __syncthreads();

    const int rw = wid * 16;
    const uint32_t aQ = (uint32_t)((rw + (lane & 15)) * FQSTR + ((lane >> 4) << 3)) * 2;
    uint32_t qfh[4][4], qfl[4][4];
#pragma unroll
    for (int kk = 0; kk < 4; ++kk) {
        LDSM4(qfh[kk], smb + F_QHI + aQ + kk * 32);
        LDSM4(qfl[kk], smb + F_QLO + aQ + kk * 32);
    }

    const uint32_t bkbase = (uint32_t)(((lane & 7) + ((lane >> 4) << 3)) * FQSTR
                                       + (((lane >> 3) & 1) << 3)) * 2;
    const uint32_t bvbase = (uint32_t)(((lane & 7) + ((lane >> 4) << 3)) * FVSTR
                                       + (((lane >> 3) & 1) << 3)) * 2;

    const int rloc = lane >> 2;
    const float mi0 = mask[b * NN + i0 + rw + rloc];
    const float mi1 = mask[b * NN + i0 + rw + rloc + 8];
    const bool rv0 = (mi0 != 0.f);
    const bool rv1 = (mi1 != 0.f);
    float m0 = -1e30f, m1 = -1e30f, l0 = 0.f, l1 = 0.f;
    float oacc[8][4];
#pragma unroll
    for (int i = 0; i < 8; ++i)
#pragma unroll
        for (int j = 0; j < 4; ++j) oacc[i][j] = 0.f;

    const float* smask = (const float*)smem;

    for (int kt = 0; kt < 8; ++kt) {
        if (kt + 1 < 8) {
            const int st = (kt + 1) & 1;
            const int j0 = (kt + 1) * 128;
#pragma unroll
            for (int t = 0; t < 4; ++t) {
                const int idx = tid + t * 256;
                const int row = idx >> 3;
                const int col = (idx & 7) << 3;
                const uint32_t so = (uint32_t)(row * FQSTR + col) * 2;
                CP16(smb + F_K(st) + so,          kH + (size_t)(j0 + row) * DHH + col);
                CP16(smb + F_K(st) + FQTILE + so, kL + (size_t)(j0 + row) * DHH + col);
            }
#pragma unroll
            for (int t = 0; t < 4; ++t) {
                const int idx = tid + t * 256;
                const int vr = idx >> 4;
                const int vc = (idx & 15) << 3;
                const uint32_t so = (uint32_t)(vr * FVSTR + vc) * 2;
                CP16(smb + F_V(st) + so,          vH + (size_t)vr * NN + j0 + vc);
                CP16(smb + F_V(st) + FVTILE + so, vL + (size_t)vr * NN + j0 + vc);
            }
            CP_COMMIT();
        }

        const uint32_t kbh = smb + F_K(kt & 1);
        const uint32_t kbl = kbh + FQTILE;
        const uint32_t vbh = smb + F_V(kt & 1);
        const uint32_t vbl = vbh + FVTILE;

        float sacc[16][4];
#pragma unroll
        for (int i = 0; i < 16; ++i)
#pragma unroll
            for (int j = 0; j < 4; ++j) sacc[i][j] = 0.f;
#pragma unroll
        for (int kk = 0; kk < 4; ++kk) {
            const uint32_t kb = kk * 32;
#pragma unroll
            for (int p = 0; p < 8; ++p) {
                uint32_t tbh[4], tbl[4];
                LDSM4(tbh, kbh + bkbase + p * 2304 + kb);
                LDSM4(tbl, kbl + bkbase + p * 2304 + kb);
                MMA_BF16(sacc[2 * p],     qfh[kk], tbh);
                MMA_BF16(sacc[2 * p + 1], qfh[kk], tbh + 2);
                MMA_BF16(sacc[2 * p],     qfh[kk], tbl);
                MMA_BF16(sacc[2 * p + 1], qfh[kk], tbl + 2);
                MMA_BF16(sacc[2 * p],     qfl[kk], tbh);
                MMA_BF16(sacc[2 * p + 1], qfl[kk], tbh + 2);
            }
        }

        const int kt128 = kt * 128;
        float tmax0 = -1e30f, tmax1 = -1e30f;
#pragma unroll
        for (int nt = 0; nt < 16; ++nt) {
            const float2 mv = *(const float2*)(smask + kt128 + nt * 8 + ((lane & 3) << 1));
            const bool g0 = (mv.x != 0.f);
            const bool g1 = (mv.y != 0.f);
            float s0 = (rv0 && g0) ? sacc[nt][0] : -1e30f;
            float s1 = (rv0 && g1) ? sacc[nt][1] : -1e30f;
            float s2 = (rv1 && g0) ? sacc[nt][2] : -1e30f;
            float s3 = (rv1 && g1) ? sacc[nt][3] : -1e30f;
            sacc[nt][0] = s0; sacc[nt][1] = s1; sacc[nt][2] = s2; sacc[nt][3] = s3;
            tmax0 = fmaxf(tmax0, fmaxf(s0, s1));
            tmax1 = fmaxf(tmax1, fmaxf(s2, s3));
        }
        tmax0 = fmaxf(tmax0, __shfl_xor_sync(0xffffffffu, tmax0, 1));
        tmax0 = fmaxf(tmax0, __shfl_xor_sync(0xffffffffu, tmax0, 2));
        tmax1 = fmaxf(tmax1, __shfl_xor_sync(0xffffffffu, tmax1, 1));
        tmax1 = fmaxf(tmax1, __shfl_xor_sync(0xffffffffu, tmax1, 2));
        const float mn0 = fmaxf(m0, tmax0);
        const float mn1 = fmaxf(m1, tmax1);
        const float sc0 = __expf(m0 - mn0);
        const float sc1 = __expf(m1 - mn1);
        m0 = mn0; m1 = mn1;

        float ls0 = 0.f, ls1 = 0.f;
#pragma unroll
        for (int nt = 0; nt < 16; ++nt) {
            float e0 = (sacc[nt][0] > -1e29f) ? __expf(sacc[nt][0] - mn0) : 0.f;
            float e1 = (sacc[nt][1] > -1e29f) ? __expf(sacc[nt][1] - mn0) : 0.f;
            float e2 = (sacc[nt][2] > -1e29f) ? __expf(sacc[nt][2] - mn1) : 0.f;
            float e3 = (sacc[nt][3] > -1e29f) ? __expf(sacc[nt][3] - mn1) : 0.f;
            sacc[nt][0] = e0; sacc[nt][1] = e1; sacc[nt][2] = e2; sacc[nt][3] = e3;
            ls0 += e0 + e1; ls1 += e2 + e3;
        }
        ls0 += __shfl_xor_sync(0xffffffffu, ls0, 1);
        ls0 += __shfl_xor_sync(0xffffffffu, ls0, 2);
        ls1 += __shfl_xor_sync(0xffffffffu, ls1, 1);
        ls1 += __shfl_xor_sync(0xffffffffu, ls1, 2);
        l0 = l0 * sc0 + ls0;
        l1 = l1 * sc1 + ls1;
#pragma unroll
        for (int no = 0; no < 8; ++no) {
            oacc[no][0] *= sc0; oacc[no][1] *= sc0;
            oacc[no][2] *= sc1; oacc[no][3] *= sc1;
        }

#pragma unroll
        for (int kc = 0; kc < 8; ++kc) {
            uint32_t pah[4], pal[4];
            cvt_hilo(sacc[2 * kc][0],     sacc[2 * kc][1],     pah[0], pal[0]);
            cvt_hilo(sacc[2 * kc][2],     sacc[2 * kc][3],     pah[1], pal[1]);
            cvt_hilo(sacc[2 * kc + 1][0], sacc[2 * kc + 1][1], pah[2], pal[2]);
            cvt_hilo(sacc[2 * kc + 1][2], sacc[2 * kc + 1][3], pah[3], pal[3]);
#pragma unroll
            for (int dv = 0; dv < 4; ++dv) {
                uint32_t vb[4], vl[4];
                LDSM4(vb, vbh + bvbase + dv * 4352 + kc * 32);
                LDSM4(vl, vbl + bvbase + dv * 4352 + kc * 32);
                MMA_BF16(oacc[2 * dv],     pah, vb);
                MMA_BF16(oacc[2 * dv + 1], pah, vb + 2);
                MMA_BF16(oacc[2 * dv],     pah, vl);
                MMA_BF16(oacc[2 * dv + 1], pah, vl + 2);
                MMA_BF16(oacc[2 * dv],     pal, vb);
                MMA_BF16(oacc[2 * dv + 1], pal, vb + 2);
            }
        }
        CP_WAIT0();
        __syncthreads();
    }

    const float inv0 = (l0 > 0.f) ? 1.f / l0 : 0.f;
    const float inv1 = (l1 > 0.f) ? 1.f / l1 : 0.f;
    const int r0g = i0 + rw + rloc;
#pragma unroll
    for (int no = 0; no < 8; ++no) {
        const size_t c = (size_t)h * 64 + no * 8 + ((lane & 3) << 1);
        *(float2*)(ao + ((size_t)b * NN + r0g) * INNERC + c) =
            make_float2(oacc[no][0] * inv0, oacc[no][1] * inv0);
        *(float2*)(ao + ((size_t)b * NN + r0g + 8) * INNERC + c) =
            make_float2(oacc[no][2] * inv1, oacc[no][3] * inv1);
    }
}

// ---------------------------------------------------------------------------
extern "C" void kernel_launch(void* const* d_in, const int* in_sizes, int n_in,
                              void* d_out, int out_size)
{
    const float* x      = (const float*)d_in[0];
    const float* mask   = (const float*)d_in[1];
    const float* w_qkv  = (const float*)d_in[2];
    const float* w_out  = (const float*)d_in[3];
    const float* b_out  = (const float*)d_in[4];
    float* out = (float*)d_out;

    int8_t *xh8, *xl8, *wqh8, *wql8, *woh8, *wol8, *aoh8, *aol8;
    float *sx, *sao, *ao;
    unsigned *tmq, *tmo;
    __nv_bfloat16 *qhi, *qlo, *khi, *klo, *vThi, *vTlo;
    cudaGetSymbolAddress((void**)&xh8, g_xh8);
    cudaGetSymbolAddress((void**)&xl8, g_xl8);
    cudaGetSymbolAddress((void**)&sx, g_sx);
    cudaGetSymbolAddress((void**)&wqh8, g_wqh8);
    cudaGetSymbolAddress((void**)&wql8, g_wql8);
    cudaGetSymbolAddress((void**)&tmq, g_tmq);
    cudaGetSymbolAddress((void**)&woh8, g_woh8);
    cudaGetSymbolAddress((void**)&wol8, g_wol8);
    cudaGetSymbolAddress((void**)&tmo, g_tmo);
    cudaGetSymbolAddress((void**)&aoh8, g_aoh8);
    cudaGetSymbolAddress((void**)&aol8, g_aol8);
    cudaGetSymbolAddress((void**)&sao, g_sao);
    cudaGetSymbolAddress((void**)&ao, g_ao);
    cudaGetSymbolAddress((void**)&qhi, g_qhi);
    cudaGetSymbolAddress((void**)&qlo, g_qlo);
    cudaGetSymbolAddress((void**)&khi, g_khi);
    cudaGetSymbolAddress((void**)&klo, g_klo);
    cudaGetSymbolAddress((void**)&vThi, g_vThi);
    cudaGetSymbolAddress((void**)&vTlo, g_vTlo);

    cudaFuncSetAttribute(gemm_qkv_i8, cudaFuncAttributeMaxDynamicSharedMemorySize,
                         I8_SMEM_BYTES);
    cudaFuncSetAttribute(gemm_out_i8, cudaFuncAttributeMaxDynamicSharedMemorySize,
                         I8_SMEM_BYTES);
    cudaFuncSetAttribute(flash_tc, cudaFuncAttributeMaxDynamicSharedMemorySize,
                         FLASH_SMEM);

    // 0) quantize x and weights
    rowquant1024<<<MM, 256>>>(x, xh8, xl8, sx);
    colmax_kernel<<<dim3(QKVC / 256, 8), 256>>>(w_qkv, tmq, DD, QKVC);
    quantT_kernel<<<dim3(QKVC / 32, DD / 32), dim3(32, 8)>>>(w_qkv, tmq, wqh8, wql8,
                                                             DD, QKVC);
    colmax_kernel<<<dim3(INNERC / 256, 8), 256>>>(w_out, tmo, INNERC, INNERC);
    quantT_kernel<<<dim3(INNERC / 32, INNERC / 32), dim3(32, 8)>>>(w_out, tmo,
                                                                   woh8, wol8,
                                                                   INNERC, INNERC);
    // 1) qkv projection (int8 tensor cores) -> q/k bf16 hi/lo + v transposed
    gemm_qkv_i8<<<dim3(QKVC / 128, MM / 128), 512, I8_SMEM_BYTES>>>(
        xh8, xl8, sx, wqh8, wql8, tmq, qhi, qlo, khi, klo, vThi, vTlo);
    // 2) fused masked flash attention -> ao fp32
    flash_tc<<<dim3(NN / 128, BHC), 256, FLASH_SMEM>>>(
        qhi, qlo, khi, klo, vThi, vTlo, mask, ao);
    // 3) quantize ao, out projection (int8 tensor cores)
    rowquant1024<<<MM, 256>>>(ao, aoh8, aol8, sao);
    gemm_out_i8<<<dim3(INNERC / 128, MM / 128), 512, I8_SMEM_BYTES>>>(
        aoh8, aol8, sao, woh8, wol8, tmo, b_out, out, INNERC);
}

// round 13
// speedup vs baseline: 1.9201x; 1.9201x over previous
#include <cuda_runtime.h>
#include <cuda_bf16.h>
#include <math.h>
#include <cstdint>

// Problem constants
#define BB 4
#define NN 1024
#define DD 1024
#define HH 16
#define DHH 64
#define INNERC 1024          // HH*DHH
#define QKVC 3072            // 3*INNERC
#define MM 4096              // BB*NN
#define BHC 64               // BB*HH
#define NSM 148

// ---------------------------------------------------------------------------
// Scratch (__device__ globals; no allocation allowed)
// ---------------------------------------------------------------------------
__device__ __nv_bfloat16 g_xhi[(size_t)MM * DD];
__device__ __nv_bfloat16 g_xlo[(size_t)MM * DD];
__device__ __nv_bfloat16 g_wqkvThi[(size_t)QKVC * DD];
__device__ __nv_bfloat16 g_wqkvTlo[(size_t)QKVC * DD];
__device__ __nv_bfloat16 g_woutThi[(size_t)INNERC * INNERC];
__device__ __nv_bfloat16 g_woutTlo[(size_t)INNERC * INNERC];

// q/k in [B,H,N,DH] bf16 hi/lo (q pre-scaled by 0.125)
__device__ __nv_bfloat16 g_qhi[(size_t)BHC * NN * DHH];
__device__ __nv_bfloat16 g_qlo[(size_t)BHC * NN * DHH];
__device__ __nv_bfloat16 g_khi[(size_t)BHC * NN * DHH];
__device__ __nv_bfloat16 g_klo[(size_t)BHC * NN * DHH];
// v stored directly transposed: [B,H,DH,N]
__device__ __nv_bfloat16 g_vThi[(size_t)BHC * DHH * NN];
__device__ __nv_bfloat16 g_vTlo[(size_t)BHC * DHH * NN];
// attention output split, [B*N, INNER]
__device__ __nv_bfloat16 g_aohi[(size_t)MM * INNERC];
__device__ __nv_bfloat16 g_aolo[(size_t)MM * INNERC];

// ---------------------------------------------------------------------------
// PTX helpers (sm_80-compatible; compile on plain compute_103)
// ---------------------------------------------------------------------------
__device__ __forceinline__ uint32_t smem_u32(const void* p) {
    uint32_t a;
    asm("{ .reg .u64 t; cvta.to.shared.u64 t, %1; cvt.u32.u64 %0, t; }"
        : "=r"(a) : "l"(p));
    return a;
}
#define LDSM4(r, addr) \
    asm volatile("ldmatrix.sync.aligned.m8n8.x4.shared.b16 {%0,%1,%2,%3}, [%4];" \
        : "=r"((r)[0]), "=r"((r)[1]), "=r"((r)[2]), "=r"((r)[3]) : "r"(addr))
#define MMA_BF16(d, a, b) \
    asm volatile("mma.sync.aligned.m16n8k16.row.col.f32.bf16.bf16.f32 " \
        "{%0,%1,%2,%3}, {%4,%5,%6,%7}, {%8,%9}, {%0,%1,%2,%3};" \
        : "+f"((d)[0]), "+f"((d)[1]), "+f"((d)[2]), "+f"((d)[3]) \
        : "r"((a)[0]), "r"((a)[1]), "r"((a)[2]), "r"((a)[3]), \
          "r"((b)[0]), "r"((b)[1]))
#define CP16(saddr, g) \
    asm volatile("cp.async.cg.shared.global [%0], [%1], 16;" :: "r"(saddr), "l"(g))
#define CP_COMMIT() asm volatile("cp.async.commit_group;" ::: "memory")
#define CP_WAIT0()  asm volatile("cp.async.wait_group 0;" ::: "memory")

__device__ __forceinline__ void store_hilo2(
    __nv_bfloat16* hb, __nv_bfloat16* lb, size_t idx, float a, float b)
{
    __nv_bfloat16 h0 = __float2bfloat16(a);
    __nv_bfloat16 h1 = __float2bfloat16(b);
    *(__nv_bfloat162*)(hb + idx) = __nv_bfloat162(h0, h1);
    *(__nv_bfloat162*)(lb + idx) =
        __nv_bfloat162(__float2bfloat16(a - __bfloat162float(h0)),
                       __float2bfloat16(b - __bfloat162float(h1)));
}
__device__ __forceinline__ void store_hilo1(
    __nv_bfloat16* hb, __nv_bfloat16* lb, size_t idx, float a)
{
    __nv_bfloat16 h0 = __float2bfloat16(a);
    hb[idx] = h0;
    lb[idx] = __float2bfloat16(a - __bfloat162float(h0));
}
__device__ __forceinline__ void cvt_hilo(float a, float b, uint32_t& h, uint32_t& l)
{
    __nv_bfloat16 ha = __float2bfloat16(a);
    __nv_bfloat16 hbb = __float2bfloat16(b);
    __nv_bfloat162 hp(ha, hbb);
    h = *(uint32_t*)&hp;
    __nv_bfloat162 lp(__float2bfloat16(a - __bfloat162float(ha)),
                      __float2bfloat16(b - __bfloat162float(hbb)));
    l = *(uint32_t*)&lp;
}

// ---------------------------------------------------------------------------
// split / splitT (prep kernels)
// ---------------------------------------------------------------------------
__global__ void __launch_bounds__(256) split_kernel(
    const float* __restrict__ in, __nv_bfloat16* __restrict__ hi,
    __nv_bfloat16* __restrict__ lo, int n4)
{
    int i = blockIdx.x * 256 + threadIdx.x;
    if (i >= n4) return;
    float4 v = *(const float4*)(in + i * 4);
    store_hilo2(hi, lo, (size_t)i * 4, v.x, v.y);
    store_hilo2(hi, lo, (size_t)i * 4 + 2, v.z, v.w);
}

__global__ void __launch_bounds__(256) splitT_kernel(
    const float* __restrict__ in, __nv_bfloat16* __restrict__ hiT,
    __nv_bfloat16* __restrict__ loT, int R, int C)
{
    __shared__ float t[32][33];
    const int c = blockIdx.x * 32 + threadIdx.x;
#pragma unroll
    for (int j = 0; j < 4; ++j) {
        int r = blockIdx.y * 32 + threadIdx.y + j * 8;
        t[threadIdx.y + j * 8][threadIdx.x] = in[(size_t)r * C + c];
    }
    __syncthreads();
    const int rr = blockIdx.y * 32 + threadIdx.x;
#pragma unroll
    for (int j = 0; j < 4; ++j) {
        int cc = blockIdx.x * 32 + threadIdx.y + j * 8;
        float v = t[threadIdx.x][threadIdx.y + j * 8];
        __nv_bfloat16 h = __float2bfloat16(v);
        hiT[(size_t)cc * R + rr] = h;
        loT[(size_t)cc * R + rr] = __float2bfloat16(v - __bfloat162float(h));
    }
}

// ---------------------------------------------------------------------------
// GEMM tiling constants (128x128 CTA tile, BK=32, 16 warps of 32x32, 2-stage)
// ---------------------------------------------------------------------------
#define TSTRIDE 40
#define TILEB (128 * TSTRIDE * 2)
#define STAGEB (4 * TILEB)                  // 40960
#define GEMM_SMEM_BYTES (2 * STAGEB)        // 81920

// ---------------------------------------------------------------------------
// out-projection GEMM (fp32 out + bias); persistent CTAs, 32x32 warp tiles
// NT tiles = (Ncols/128) * (M/128); tile -> (m, n) n-major
// ---------------------------------------------------------------------------
__global__ void __launch_bounds__(512, 1) gemm_mma(
    const __nv_bfloat16* __restrict__ Ahi, const __nv_bfloat16* __restrict__ Alo,
    const __nv_bfloat16* __restrict__ Bthi, const __nv_bfloat16* __restrict__ Btlo,
    const float* __restrict__ bias, float* __restrict__ C,
    int M, int Ncols, int K)
{
    extern __shared__ char smem[];
    const uint32_t smb = smem_u32(smem);
    const int tid = threadIdx.x;
    const int lane = tid & 31;
    const int wid = tid >> 5;
    const int mw = wid >> 2;
    const int nw = wid & 3;

    const int ntn = Ncols >> 7;
    const int NT = (M >> 7) * ntn;

    const int grow = tid >> 2;
    const int gcol = (tid & 3) << 3;
    const uint32_t stb = (uint32_t)(grow * TSTRIDE + gcol) * 2;

    uint32_t aoff[2];
#pragma unroll
    for (int mt = 0; mt < 2; ++mt)
        aoff[mt] = (uint32_t)((mw * 32 + mt * 16 + (lane & 15)) * TSTRIDE
                              + ((lane >> 4) << 3)) * 2;
    const int brow = nw * 32 + (lane & 7) + ((lane >> 4) << 3);
    const int bcol = ((lane >> 3) & 1) << 3;
    uint32_t boff[2];
    boff[0] = (uint32_t)(brow * TSTRIDE + bcol) * 2;
    boff[1] = (uint32_t)((brow + 16) * TSTRIDE + bcol) * 2;

    const int nst = K >> 5;

    for (int tile = blockIdx.x; tile < NT; tile += NSM) {
        const int m0 = (tile / ntn) << 7;
        const int n0 = (tile % ntn) << 7;
        const __nv_bfloat16* gAh = Ahi  + (size_t)(m0 + grow) * K + gcol;
        const __nv_bfloat16* gAl = Alo  + (size_t)(m0 + grow) * K + gcol;
        const __nv_bfloat16* gBh = Bthi + (size_t)(n0 + grow) * K + gcol;
        const __nv_bfloat16* gBl = Btlo + (size_t)(n0 + grow) * K + gcol;

        float acc[2][4][4];
#pragma unroll
        for (int i = 0; i < 2; ++i)
#pragma unroll
            for (int j = 0; j < 4; ++j)
#pragma unroll
                for (int k = 0; k < 4; ++k) acc[i][j][k] = 0.f;

        {
            const uint32_t d = smb + stb;
            CP16(d,             gAh);
            CP16(d + TILEB,     gAl);
            CP16(d + 2 * TILEB, gBh);
            CP16(d + 3 * TILEB, gBl);
            CP_COMMIT(); CP_WAIT0();
        }
        __syncthreads();

        for (int s = 0; s < nst; ++s) {
            if (s + 1 < nst) {
                const int k0 = (s + 1) << 5;
                const uint32_t d = smb + ((s + 1) & 1) * STAGEB + stb;
                CP16(d,             gAh + k0);
                CP16(d + TILEB,     gAl + k0);
                CP16(d + 2 * TILEB, gBh + k0);
                CP16(d + 3 * TILEB, gBl + k0);
                CP_COMMIT();
            }
            const uint32_t sb = smb + (s & 1) * STAGEB;
#pragma unroll
            for (int kk = 0; kk < 2; ++kk) {
                const uint32_t kb = kk * 32;
                uint32_t ah[2][4], al[2][4], bh[4][2], bl[4][2];
#pragma unroll
                for (int mt = 0; mt < 2; ++mt) {
                    LDSM4(ah[mt], sb + aoff[mt] + kb);
                    LDSM4(al[mt], sb + TILEB + aoff[mt] + kb);
                }
#pragma unroll
                for (int p = 0; p < 2; ++p) {
                    uint32_t t4[4];
                    LDSM4(t4, sb + 2 * TILEB + boff[p] + kb);
                    bh[2 * p][0] = t4[0]; bh[2 * p][1] = t4[1];
                    bh[2 * p + 1][0] = t4[2]; bh[2 * p + 1][1] = t4[3];
                    LDSM4(t4, sb + 3 * TILEB + boff[p] + kb);
                    bl[2 * p][0] = t4[0]; bl[2 * p][1] = t4[1];
                    bl[2 * p + 1][0] = t4[2]; bl[2 * p + 1][1] = t4[3];
                }
#pragma unroll
                for (int mt = 0; mt < 2; ++mt)
#pragma unroll
                    for (int nt = 0; nt < 4; ++nt)
                        MMA_BF16(acc[mt][nt], ah[mt], bh[nt]);
#pragma unroll
                for (int mt = 0; mt < 2; ++mt)
#pragma unroll
                    for (int nt = 0; nt < 4; ++nt)
                        MMA_BF16(acc[mt][nt], ah[mt], bl[nt]);
#pragma unroll
                for (int mt = 0; mt < 2; ++mt)
#pragma unroll
                    for (int nt = 0; nt < 4; ++nt)
                        MMA_BF16(acc[mt][nt], al[mt], bh[nt]);
            }
            CP_WAIT0();
            __syncthreads();
        }

#pragma unroll
        for (int mt = 0; mt < 2; ++mt) {
            const int r0 = m0 + mw * 32 + mt * 16 + (lane >> 2);
#pragma unroll
            for (int nt = 0; nt < 4; ++nt) {
                const int cc = n0 + nw * 32 + nt * 8 + ((lane & 3) << 1);
                float2 v0 = make_float2(acc[mt][nt][0], acc[mt][nt][1]);
                float2 v1 = make_float2(acc[mt][nt][2], acc[mt][nt][3]);
                if (bias) {
                    float2 bv = *(const float2*)(bias + cc);
                    v0.x += bv.x; v0.y += bv.y;
                    v1.x += bv.x; v1.y += bv.y;
                }
                *(float2*)(C + (size_t)r0 * Ncols + cc) = v0;
                *(float2*)(C + (size_t)(r0 + 8) * Ncols + cc) = v1;
            }
        }
    }
}

// ---------------------------------------------------------------------------
// qkv GEMM: persistent CTAs, 32x32 warp tiles; epilogue writes q(*0.125)/k in
// [B,H,N,DH] and v DIRECTLY TRANSPOSED into [B,H,DH,N]
// ---------------------------------------------------------------------------
__global__ void __launch_bounds__(512, 1) gemm_qkv(
    const __nv_bfloat16* __restrict__ Ahi, const __nv_bfloat16* __restrict__ Alo,
    const __nv_bfloat16* __restrict__ Bthi, const __nv_bfloat16* __restrict__ Btlo,
    __nv_bfloat16* __restrict__ qhi, __nv_bfloat16* __restrict__ qlo,
    __nv_bfloat16* __restrict__ khi, __nv_bfloat16* __restrict__ klo,
    __nv_bfloat16* __restrict__ vThi, __nv_bfloat16* __restrict__ vTlo)
{
    extern __shared__ char smem[];
    const uint32_t smb = smem_u32(smem);
    const int tid = threadIdx.x;
    const int lane = tid & 31;
    const int wid = tid >> 5;
    const int mw = wid >> 2;
    const int nw = wid & 3;
    const int K = DD;
    const int NT = (QKVC >> 7) * (MM >> 7);   // 24 * 32 = 768

    const int grow = tid >> 2;
    const int gcol = (tid & 3) << 3;
    const uint32_t stb = (uint32_t)(grow * TSTRIDE + gcol) * 2;

    uint32_t aoff[2];
#pragma unroll
    for (int mt = 0; mt < 2; ++mt)
        aoff[mt] = (uint32_t)((mw * 32 + mt * 16 + (lane & 15)) * TSTRIDE
                              + ((lane >> 4) << 3)) * 2;
    const int brow = nw * 32 + (lane & 7) + ((lane >> 4) << 3);
    const int bcol = ((lane >> 3) & 1) << 3;
    uint32_t boff[2];
    boff[0] = (uint32_t)(brow * TSTRIDE + bcol) * 2;
    boff[1] = (uint32_t)((brow + 16) * TSTRIDE + bcol) * 2;

    const int nst = K >> 5;

    for (int tile = blockIdx.x; tile < NT; tile += NSM) {
        const int m0 = (tile / 24) << 7;
        const int n0 = (tile % 24) << 7;
        const __nv_bfloat16* gAh = Ahi  + (size_t)(m0 + grow) * K + gcol;
        const __nv_bfloat16* gAl = Alo  + (size_t)(m0 + grow) * K + gcol;
        const __nv_bfloat16* gBh = Bthi + (size_t)(n0 + grow) * K + gcol;
        const __nv_bfloat16* gBl = Btlo + (size_t)(n0 + grow) * K + gcol;

        float acc[2][4][4];
#pragma unroll
        for (int i = 0; i < 2; ++i)
#pragma unroll
            for (int j = 0; j < 4; ++j)
#pragma unroll
                for (int k = 0; k < 4; ++k) acc[i][j][k] = 0.f;

        {
            const uint32_t d = smb + stb;
            CP16(d,             gAh);
            CP16(d + TILEB,     gAl);
            CP16(d + 2 * TILEB, gBh);
            CP16(d + 3 * TILEB, gBl);
            CP_COMMIT(); CP_WAIT0();
        }
        __syncthreads();

        for (int s = 0; s < nst; ++s) {
            if (s + 1 < nst) {
                const int k0 = (s + 1) << 5;
                const uint32_t d = smb + ((s + 1) & 1) * STAGEB + stb;
                CP16(d,             gAh + k0);
                CP16(d + TILEB,     gAl + k0);
                CP16(d + 2 * TILEB, gBh + k0);
                CP16(d + 3 * TILEB, gBl + k0);
                CP_COMMIT();
            }
            const uint32_t sb = smb + (s & 1) * STAGEB;
#pragma unroll
            for (int kk = 0; kk < 2; ++kk) {
                const uint32_t kb = kk * 32;
                uint32_t ah[2][4], al[2][4], bh[4][2], bl[4][2];
#pragma unroll
                for (int mt = 0; mt < 2; ++mt) {
                    LDSM4(ah[mt], sb + aoff[mt] + kb);
                    LDSM4(al[mt], sb + TILEB + aoff[mt] + kb);
                }
#pragma unroll
                for (int p = 0; p < 2; ++p) {
                    uint32_t t4[4];
                    LDSM4(t4, sb + 2 * TILEB + boff[p] + kb);
                    bh[2 * p][0] = t4[0]; bh[2 * p][1] = t4[1];
                    bh[2 * p + 1][0] = t4[2]; bh[2 * p + 1][1] = t4[3];
                    LDSM4(t4, sb + 3 * TILEB + boff[p] + kb);
                    bl[2 * p][0] = t4[0]; bl[2 * p][1] = t4[1];
                    bl[2 * p + 1][0] = t4[2]; bl[2 * p + 1][1] = t4[3];
                }
#pragma unroll
                for (int mt = 0; mt < 2; ++mt)
#pragma unroll
                    for (int nt = 0; nt < 4; ++nt)
                        MMA_BF16(acc[mt][nt], ah[mt], bh[nt]);
#pragma unroll
                for (int mt = 0; mt < 2; ++mt)
#pragma unroll
                    for (int nt = 0; nt < 4; ++nt)
                        MMA_BF16(acc[mt][nt], ah[mt], bl[nt]);
#pragma unroll
                for (int mt = 0; mt < 2; ++mt)
#pragma unroll
                    for (int nt = 0; nt < 4; ++nt)
                        MMA_BF16(acc[mt][nt], al[mt], bh[nt]);
            }
            CP_WAIT0();
            __syncthreads();
        }

        // epilogue: q (*0.125) / k in [B,H,N,DH]; v transposed into [B,H,DH,N]
#pragma unroll
        for (int nt = 0; nt < 4; ++nt) {
            const int cc = n0 + nw * 32 + nt * 8 + ((lane & 3) << 1);
            const int sec = cc >> 10;
            const int h = (cc & 1023) >> 6;
            const int d = cc & 63;
#pragma unroll
            for (int mt = 0; mt < 2; ++mt) {
                const int r0 = m0 + mw * 32 + mt * 16 + (lane >> 2);
                const int b = r0 >> 10;
                const int n = r0 & 1023;
                const size_t bhbase = ((size_t)b * HH + h);
                if (sec == 0) {
                    store_hilo2(qhi, qlo, (bhbase * NN + n) * DHH + d,
                                acc[mt][nt][0] * 0.125f, acc[mt][nt][1] * 0.125f);
                    store_hilo2(qhi, qlo, (bhbase * NN + n + 8) * DHH + d,
                                acc[mt][nt][2] * 0.125f, acc[mt][nt][3] * 0.125f);
                } else if (sec == 1) {
                    store_hilo2(khi, klo, (bhbase * NN + n) * DHH + d,
                                acc[mt][nt][0], acc[mt][nt][1]);
                    store_hilo2(khi, klo, (bhbase * NN + n + 8) * DHH + d,
                                acc[mt][nt][2], acc[mt][nt][3]);
                } else {
                    const size_t vb = bhbase * DHH;
                    store_hilo1(vThi, vTlo, (vb + d) * NN + n,         acc[mt][nt][0]);
                    store_hilo1(vThi, vTlo, (vb + d + 1) * NN + n,     acc[mt][nt][1]);
                    store_hilo1(vThi, vTlo, (vb + d) * NN + n + 8,     acc[mt][nt][2]);
                    store_hilo1(vThi, vTlo, (vb + d + 1) * NN + n + 8, acc[mt][nt][3]);
                }
            }
        }
    }
}

// ---------------------------------------------------------------------------
// flash_tc: fused masked attention, persistent CTAs over (bh, 128-row Q tile)
// ---------------------------------------------------------------------------
#define FQSTR 72
#define FQTILE 18432                      // 128*72*2
#define FVSTR 136
#define FVTILE 17408                      // 64*136*2
#define F_MASK 0
#define F_QHI 4096
#define F_QLO (F_QHI + FQTILE)
#define F_K(st) (40960 + (st) * 2 * FQTILE)           // hi at +0, lo at +FQTILE
#define F_V(st) (114688 + (st) * 2 * FVTILE)          // hi at +0, lo at +FVTILE
#define FLASH_SMEM 184320

__global__ void __launch_bounds__(256, 1) flash_tc(
    const __nv_bfloat16* __restrict__ qhi, const __nv_bfloat16* __restrict__ qlo,
    const __nv_bfloat16* __restrict__ khi, const __nv_bfloat16* __restrict__ klo,
    const __nv_bfloat16* __restrict__ vThi, const __nv_bfloat16* __restrict__ vTlo,
    const float* __restrict__ mask,
    __nv_bfloat16* __restrict__ aohi, __nv_bfloat16* __restrict__ aolo)
{
    extern __shared__ char smem[];
    const uint32_t smb = smem_u32(smem);
    const int tid = threadIdx.x;
    const int lane = tid & 31;
    const int wid = tid >> 5;
    const int rw = wid * 16;
    const int rloc = lane >> 2;

    const uint32_t bkbase = (uint32_t)(((lane & 7) + ((lane >> 4) << 3)) * FQSTR
                                       + (((lane >> 3) & 1) << 3)) * 2;
    const uint32_t bvbase = (uint32_t)(((lane & 7) + ((lane >> 4) << 3)) * FVSTR
                                       + (((lane >> 3) & 1) << 3)) * 2;
    const uint32_t aQ = (uint32_t)((rw + (lane & 15)) * FQSTR + ((lane >> 4) << 3)) * 2;
    const float* smask = (const float*)smem;

    for (int tile = blockIdx.x; tile < 512; tile += NSM) {
        const int bh = tile >> 3;
        const int i0 = (tile & 7) << 7;
        const int b = bh >> 4;
        const int h = bh & 15;
        const size_t hb = (size_t)bh * NN * DHH;
        const __nv_bfloat16* kH = khi + hb;
        const __nv_bfloat16* kL = klo + hb;
        const __nv_bfloat16* vH = vThi + (size_t)bh * DHH * NN;
        const __nv_bfloat16* vL = vTlo + (size_t)bh * DHH * NN;

        // ---- prologue: mask + Q + K0 + V0 via cp.async
        CP16(smb + F_MASK + tid * 16, mask + b * NN + tid * 4);
#pragma unroll
        for (int t = 0; t < 4; ++t) {
            const int idx = tid + t * 256;
            const int row = idx >> 3;
            const int col = (idx & 7) << 3;
            const uint32_t so = (uint32_t)(row * FQSTR + col) * 2;
            CP16(smb + F_QHI + so, qhi + hb + (size_t)(i0 + row) * DHH + col);
            CP16(smb + F_QLO + so, qlo + hb + (size_t)(i0 + row) * DHH + col);
            CP16(smb + F_K(0) + so,          kH + (size_t)row * DHH + col);
            CP16(smb + F_K(0) + FQTILE + so, kL + (size_t)row * DHH + col);
        }
#pragma unroll
        for (int t = 0; t < 4; ++t) {
            const int idx = tid + t * 256;
            const int vr = idx >> 4;
            const int vc = (idx & 15) << 3;
            const uint32_t so = (uint32_t)(vr * FVSTR + vc) * 2;
            CP16(smb + F_V(0) + so,          vH + (size_t)vr * NN + vc);
            CP16(smb + F_V(0) + FVTILE + so, vL + (size_t)vr * NN + vc);
        }
        CP_COMMIT(); CP_WAIT0();
        __syncthreads();

        // ---- Q fragments (cached in regs)
        uint32_t qfh[4][4], qfl[4][4];
#pragma unroll
        for (int kk = 0; kk < 4; ++kk) {
            LDSM4(qfh[kk], smb + F_QHI + aQ + kk * 32);
            LDSM4(qfl[kk], smb + F_QLO + aQ + kk * 32);
        }

        const float mi0 = mask[b * NN + i0 + rw + rloc];
        const float mi1 = mask[b * NN + i0 + rw + rloc + 8];
        const bool rv0 = (mi0 != 0.f);
        const bool rv1 = (mi1 != 0.f);
        float m0 = -1e30f, m1 = -1e30f, l0 = 0.f, l1 = 0.f;
        float oacc[8][4];
#pragma unroll
        for (int i = 0; i < 8; ++i)
#pragma unroll
            for (int j = 0; j < 4; ++j) oacc[i][j] = 0.f;

        for (int kt = 0; kt < 8; ++kt) {
            if (kt + 1 < 8) {
                const int st = (kt + 1) & 1;
                const int j0 = (kt + 1) * 128;
#pragma unroll
                for (int t = 0; t < 4; ++t) {
                    const int idx = tid + t * 256;
                    const int row = idx >> 3;
                    const int col = (idx & 7) << 3;
                    const uint32_t so = (uint32_t)(row * FQSTR + col) * 2;
                    CP16(smb + F_K(st) + so,          kH + (size_t)(j0 + row) * DHH + col);
                    CP16(smb + F_K(st) + FQTILE + so, kL + (size_t)(j0 + row) * DHH + col);
                }
#pragma unroll
                for (int t = 0; t < 4; ++t) {
                    const int idx = tid + t * 256;
                    const int vr = idx >> 4;
                    const int vc = (idx & 15) << 3;
                    const uint32_t so = (uint32_t)(vr * FVSTR + vc) * 2;
                    CP16(smb + F_V(st) + so,          vH + (size_t)vr * NN + j0 + vc);
                    CP16(smb + F_V(st) + FVTILE + so, vL + (size_t)vr * NN + j0 + vc);
                }
                CP_COMMIT();
            }

            const uint32_t kbh = smb + F_K(kt & 1);
            const uint32_t kbl = kbh + FQTILE;
            const uint32_t vbh = smb + F_V(kt & 1);
            const uint32_t vbl = vbh + FVTILE;

            float sacc[16][4];
#pragma unroll
            for (int i = 0; i < 16; ++i)
#pragma unroll
                for (int j = 0; j < 4; ++j) sacc[i][j] = 0.f;
#pragma unroll
            for (int kk = 0; kk < 4; ++kk) {
                const uint32_t kb = kk * 32;
#pragma unroll
                for (int p = 0; p < 8; ++p) {
                    uint32_t tbh[4], tbl[4];
                    LDSM4(tbh, kbh + bkbase + p * 2304 + kb);
                    LDSM4(tbl, kbl + bkbase + p * 2304 + kb);
                    MMA_BF16(sacc[2 * p],     qfh[kk], tbh);
                    MMA_BF16(sacc[2 * p + 1], qfh[kk], tbh + 2);
                    MMA_BF16(sacc[2 * p],     qfh[kk], tbl);
                    MMA_BF16(sacc[2 * p + 1], qfh[kk], tbl + 2);
                    MMA_BF16(sacc[2 * p],     qfl[kk], tbh);
                    MMA_BF16(sacc[2 * p + 1], qfl[kk], tbh + 2);
                }
            }

            const int kt128 = kt * 128;
            float tmax0 = -1e30f, tmax1 = -1e30f;
#pragma unroll
            for (int nt = 0; nt < 16; ++nt) {
                const float2 mv = *(const float2*)(smask + kt128 + nt * 8 + ((lane & 3) << 1));
                const bool g0 = (mv.x != 0.f);
                const bool g1 = (mv.y != 0.f);
                float s0 = (rv0 && g0) ? sacc[nt][0] : -1e30f;
                float s1 = (rv0 && g1) ? sacc[nt][1] : -1e30f;
                float s2 = (rv1 && g0) ? sacc[nt][2] : -1e30f;
                float s3 = (rv1 && g1) ? sacc[nt][3] : -1e30f;
                sacc[nt][0] = s0; sacc[nt][1] = s1; sacc[nt][2] = s2; sacc[nt][3] = s3;
                tmax0 = fmaxf(tmax0, fmaxf(s0, s1));
                tmax1 = fmaxf(tmax1, fmaxf(s2, s3));
            }
            tmax0 = fmaxf(tmax0, __shfl_xor_sync(0xffffffffu, tmax0, 1));
            tmax0 = fmaxf(tmax0, __shfl_xor_sync(0xffffffffu, tmax0, 2));
            tmax1 = fmaxf(tmax1, __shfl_xor_sync(0xffffffffu, tmax1, 1));
            tmax1 = fmaxf(tmax1, __shfl_xor_sync(0xffffffffu, tmax1, 2));
            const float mn0 = fmaxf(m0, tmax0);
            const float mn1 = fmaxf(m1, tmax1);
            const float sc0 = __expf(m0 - mn0);
            const float sc1 = __expf(m1 - mn1);
            m0 = mn0; m1 = mn1;

            float ls0 = 0.f, ls1 = 0.f;
#pragma unroll
            for (int nt = 0; nt < 16; ++nt) {
                float e0 = (sacc[nt][0] > -1e29f) ? __expf(sacc[nt][0] - mn0) : 0.f;
                float e1 = (sacc[nt][1] > -1e29f) ? __expf(sacc[nt][1] - mn0) : 0.f;
                float e2 = (sacc[nt][2] > -1e29f) ? __expf(sacc[nt][2] - mn1) : 0.f;
                float e3 = (sacc[nt][3] > -1e29f) ? __expf(sacc[nt][3] - mn1) : 0.f;
                sacc[nt][0] = e0; sacc[nt][1] = e1; sacc[nt][2] = e2; sacc[nt][3] = e3;
                ls0 += e0 + e1; ls1 += e2 + e3;
            }
            ls0 += __shfl_xor_sync(0xffffffffu, ls0, 1);
            ls0 += __shfl_xor_sync(0xffffffffu, ls0, 2);
            ls1 += __shfl_xor_sync(0xffffffffu, ls1, 1);
            ls1 += __shfl_xor_sync(0xffffffffu, ls1, 2);
            l0 = l0 * sc0 + ls0;
            l1 = l1 * sc1 + ls1;
#pragma unroll
            for (int no = 0; no < 8; ++no) {
                oacc[no][0] *= sc0; oacc[no][1] *= sc0;
                oacc[no][2] *= sc1; oacc[no][3] *= sc1;
            }

#pragma unroll
            for (int kc = 0; kc < 8; ++kc) {
                uint32_t pah[4], pal[4];
                cvt_hilo(sacc[2 * kc][0],     sacc[2 * kc][1],     pah[0], pal[0]);
                cvt_hilo(sacc[2 * kc][2],     sacc[2 * kc][3],     pah[1], pal[1]);
                cvt_hilo(sacc[2 * kc + 1][0], sacc[2 * kc + 1][1], pah[2], pal[2]);
                cvt_hilo(sacc[2 * kc + 1][2], sacc[2 * kc + 1][3], pah[3], pal[3]);
#pragma unroll
                for (int dv = 0; dv < 4; ++dv) {
                    uint32_t vb[4], vl[4];
                    LDSM4(vb, vbh + bvbase + dv * 4352 + kc * 32);
                    LDSM4(vl, vbl + bvbase + dv * 4352 + kc * 32);
                    MMA_BF16(oacc[2 * dv],     pah, vb);
                    MMA_BF16(oacc[2 * dv + 1], pah, vb + 2);
                    MMA_BF16(oacc[2 * dv],     pah, vl);
                    MMA_BF16(oacc[2 * dv + 1], pah, vl + 2);
                    MMA_BF16(oacc[2 * dv],     pal, vb);
                    MMA_BF16(oacc[2 * dv + 1], pal, vb + 2);
                }
            }
            CP_WAIT0();
            __syncthreads();
        }

        const float inv0 = (l0 > 0.f) ? 1.f / l0 : 0.f;
        const float inv1 = (l1 > 0.f) ? 1.f / l1 : 0.f;
        const int r0g = i0 + rw + rloc;
#pragma unroll
        for (int no = 0; no < 8; ++no) {
            const size_t c = (size_t)h * 64 + no * 8 + ((lane & 3) << 1);
            store_hilo2(aohi, aolo, ((size_t)b * NN + r0g) * INNERC + c,
                        oacc[no][0] * inv0, oacc[no][1] * inv0);
            store_hilo2(aohi, aolo, ((size_t)b * NN + r0g + 8) * INNERC + c,
                        oacc[no][2] * inv1, oacc[no][3] * inv1);
        }
    }
}

// ---------------------------------------------------------------------------
extern "C" void kernel_launch(void* const* d_in, const int* in_sizes, int n_in,
                              void* d_out, int out_size)
{
    const float* x      = (const float*)d_in[0];
    const float* mask   = (const float*)d_in[1];
    const float* w_qkv  = (const float*)d_in[2];
    const float* w_out  = (const float*)d_in[3];
    const float* b_out  = (const float*)d_in[4];
    float* out = (float*)d_out;

    __nv_bfloat16 *xhi, *xlo, *wqhi, *wqlo, *wohi, *wolo, *aohi, *aolo;
    __nv_bfloat16 *qhi, *qlo, *khi, *klo, *vThi, *vTlo;
    cudaGetSymbolAddress((void**)&xhi, g_xhi);
    cudaGetSymbolAddress((void**)&xlo, g_xlo);
    cudaGetSymbolAddress((void**)&wqhi, g_wqkvThi);
    cudaGetSymbolAddress((void**)&wqlo, g_wqkvTlo);
    cudaGetSymbolAddress((void**)&wohi, g_woutThi);
    cudaGetSymbolAddress((void**)&wolo, g_woutTlo);
    cudaGetSymbolAddress((void**)&aohi, g_aohi);
    cudaGetSymbolAddress((void**)&aolo, g_aolo);
    cudaGetSymbolAddress((void**)&qhi, g_qhi);
    cudaGetSymbolAddress((void**)&qlo, g_qlo);
    cudaGetSymbolAddress((void**)&khi, g_khi);
    cudaGetSymbolAddress((void**)&klo, g_klo);
    cudaGetSymbolAddress((void**)&vThi, g_vThi);
    cudaGetSymbolAddress((void**)&vTlo, g_vTlo);

    cudaFuncSetAttribute(gemm_mma, cudaFuncAttributeMaxDynamicSharedMemorySize,
                         GEMM_SMEM_BYTES);
    cudaFuncSetAttribute(gemm_qkv, cudaFuncAttributeMaxDynamicSharedMemorySize,
                         GEMM_SMEM_BYTES);
    cudaFuncSetAttribute(flash_tc, cudaFuncAttributeMaxDynamicSharedMemorySize,
                         FLASH_SMEM);

    // 0) splits
    split_kernel<<<(MM * DD / 4 + 255) / 256, 256>>>(x, xhi, xlo, MM * DD / 4);
    splitT_kernel<<<dim3(QKVC / 32, DD / 32), dim3(32, 8)>>>(w_qkv, wqhi, wqlo, DD, QKVC);
    splitT_kernel<<<dim3(INNERC / 32, INNERC / 32), dim3(32, 8)>>>(w_out, wohi, wolo,
                                                                   INNERC, INNERC);
    // 1) qkv projection (persistent) -> q(*0.125)/k bf16 hi/lo + v transposed
    gemm_qkv<<<NSM, 512, GEMM_SMEM_BYTES>>>(
        xhi, xlo, wqhi, wqlo, qhi, qlo, khi, klo, vThi, vTlo);
    // 2) fused masked flash attention (persistent) -> ao bf16 hi/lo
    flash_tc<<<NSM, 256, FLASH_SMEM>>>(
        qhi, qlo, khi, klo, vThi, vTlo, mask, aohi, aolo);
    // 3) out projection (persistent)
    gemm_mma<<<NSM, 512, GEMM_SMEM_BYTES>>>(
        aohi, aolo, wohi, wolo, b_out, out, MM, INNERC, INNERC);
}

// round 14
// speedup vs baseline: 1.9533x; 1.0173x over previous
#include <cuda_runtime.h>
#include <cuda_bf16.h>
#include <math.h>
#include <cstdint>

// Problem constants
#define BB 4
#define NN 1024
#define DD 1024
#define HH 16
#define DHH 64
#define INNERC 1024          // HH*DHH
#define QKVC 3072            // 3*INNERC
#define MM 4096              // BB*NN
#define BHC 64               // BB*HH
#define NSM 148

// ---------------------------------------------------------------------------
// Scratch (__device__ globals; no allocation allowed)
// ---------------------------------------------------------------------------
__device__ __nv_bfloat16 g_xhi[(size_t)MM * DD];
__device__ __nv_bfloat16 g_xlo[(size_t)MM * DD];
__device__ __nv_bfloat16 g_wqkvThi[(size_t)QKVC * DD];
__device__ __nv_bfloat16 g_wqkvTlo[(size_t)QKVC * DD];
__device__ float g_woT[(size_t)INNERC * INNERC];        // w_out^T, tf32-rounded

// q/k in [B,H,N,DH] bf16 hi/lo (q pre-scaled by 0.125)
__device__ __nv_bfloat16 g_qhi[(size_t)BHC * NN * DHH];
__device__ __nv_bfloat16 g_qlo[(size_t)BHC * NN * DHH];
__device__ __nv_bfloat16 g_khi[(size_t)BHC * NN * DHH];
__device__ __nv_bfloat16 g_klo[(size_t)BHC * NN * DHH];
// v stored directly transposed: [B,H,DH,N]
__device__ __nv_bfloat16 g_vThi[(size_t)BHC * DHH * NN];
__device__ __nv_bfloat16 g_vTlo[(size_t)BHC * DHH * NN];
// attention output fp32 (tf32-rounded), [B*N, INNER]
__device__ float g_ao[(size_t)MM * INNERC];

// ---------------------------------------------------------------------------
// PTX helpers (sm_80-compatible; compile on plain compute_103)
// ---------------------------------------------------------------------------
__device__ __forceinline__ uint32_t smem_u32(const void* p) {
    uint32_t a;
    asm("{ .reg .u64 t; cvta.to.shared.u64 t, %1; cvt.u32.u64 %0, t; }"
        : "=r"(a) : "l"(p));
    return a;
}
#define LDSM4(r, addr) \
    asm volatile("ldmatrix.sync.aligned.m8n8.x4.shared.b16 {%0,%1,%2,%3}, [%4];" \
        : "=r"((r)[0]), "=r"((r)[1]), "=r"((r)[2]), "=r"((r)[3]) : "r"(addr))
#define MMA_BF16(d, a, b) \
    asm volatile("mma.sync.aligned.m16n8k16.row.col.f32.bf16.bf16.f32 " \
        "{%0,%1,%2,%3}, {%4,%5,%6,%7}, {%8,%9}, {%0,%1,%2,%3};" \
        : "+f"((d)[0]), "+f"((d)[1]), "+f"((d)[2]), "+f"((d)[3]) \
        : "r"((a)[0]), "r"((a)[1]), "r"((a)[2]), "r"((a)[3]), \
          "r"((b)[0]), "r"((b)[1]))
#define MMA_TF32(d, a, b) \
    asm volatile("mma.sync.aligned.m16n8k8.row.col.f32.tf32.tf32.f32 " \
        "{%0,%1,%2,%3}, {%4,%5,%6,%7}, {%8,%9}, {%0,%1,%2,%3};" \
        : "+f"((d)[0]), "+f"((d)[1]), "+f"((d)[2]), "+f"((d)[3]) \
        : "r"((a)[0]), "r"((a)[1]), "r"((a)[2]), "r"((a)[3]), \
          "r"((b)[0]), "r"((b)[1]))
#define CP16(saddr, g) \
    asm volatile("cp.async.cg.shared.global [%0], [%1], 16;" :: "r"(saddr), "l"(g))
#define CP_COMMIT() asm volatile("cp.async.commit_group;" ::: "memory")
#define CP_WAIT0()  asm volatile("cp.async.wait_group 0;" ::: "memory")

__device__ __forceinline__ float tf32rna(float x) {
    uint32_t r;
    asm("cvt.rna.tf32.f32 %0, %1;" : "=r"(r) : "f"(x));
    return __uint_as_float(r);
}
__device__ __forceinline__ void store_hilo2(
    __nv_bfloat16* hb, __nv_bfloat16* lb, size_t idx, float a, float b)
{
    __nv_bfloat16 h0 = __float2bfloat16(a);
    __nv_bfloat16 h1 = __float2bfloat16(b);
    *(__nv_bfloat162*)(hb + idx) = __nv_bfloat162(h0, h1);
    *(__nv_bfloat162*)(lb + idx) =
        __nv_bfloat162(__float2bfloat16(a - __bfloat162float(h0)),
                       __float2bfloat16(b - __bfloat162float(h1)));
}
__device__ __forceinline__ void store_hilo1(
    __nv_bfloat16* hb, __nv_bfloat16* lb, size_t idx, float a)
{
    __nv_bfloat16 h0 = __float2bfloat16(a);
    hb[idx] = h0;
    lb[idx] = __float2bfloat16(a - __bfloat162float(h0));
}
__device__ __forceinline__ void cvt_hilo(float a, float b, uint32_t& h, uint32_t& l)
{
    __nv_bfloat16 ha = __float2bfloat16(a);
    __nv_bfloat16 hbb = __float2bfloat16(b);
    __nv_bfloat162 hp(ha, hbb);
    h = *(uint32_t*)&hp;
    __nv_bfloat162 lp(__float2bfloat16(a - __bfloat162float(ha)),
                      __float2bfloat16(b - __bfloat162float(hbb)));
    l = *(uint32_t*)&lp;
}

// ---------------------------------------------------------------------------
// prep kernels
// ---------------------------------------------------------------------------
__global__ void __launch_bounds__(256) split_kernel(
    const float* __restrict__ in, __nv_bfloat16* __restrict__ hi,
    __nv_bfloat16* __restrict__ lo, int n4)
{
    int i = blockIdx.x * 256 + threadIdx.x;
    if (i >= n4) return;
    float4 v = *(const float4*)(in + i * 4);
    store_hilo2(hi, lo, (size_t)i * 4, v.x, v.y);
    store_hilo2(hi, lo, (size_t)i * 4 + 2, v.z, v.w);
}

__global__ void __launch_bounds__(256) splitT_kernel(
    const float* __restrict__ in, __nv_bfloat16* __restrict__ hiT,
    __nv_bfloat16* __restrict__ loT, int R, int C)
{
    __shared__ float t[32][33];
    const int c = blockIdx.x * 32 + threadIdx.x;
#pragma unroll
    for (int j = 0; j < 4; ++j) {
        int r = blockIdx.y * 32 + threadIdx.y + j * 8;
        t[threadIdx.y + j * 8][threadIdx.x] = in[(size_t)r * C + c];
    }
    __syncthreads();
    const int rr = blockIdx.y * 32 + threadIdx.x;
#pragma unroll
    for (int j = 0; j < 4; ++j) {
        int cc = blockIdx.x * 32 + threadIdx.y + j * 8;
        float v = t[threadIdx.x][threadIdx.y + j * 8];
        __nv_bfloat16 h = __float2bfloat16(v);
        hiT[(size_t)cc * R + rr] = h;
        loT[(size_t)cc * R + rr] = __float2bfloat16(v - __bfloat162float(h));
    }
}

// transpose + tf32 RNA rounding (for w_out)
__global__ void __launch_bounds__(256) transT_rna(
    const float* __restrict__ in, float* __restrict__ outT, int R, int C)
{
    __shared__ float t[32][33];
    const int c = blockIdx.x * 32 + threadIdx.x;
#pragma unroll
    for (int j = 0; j < 4; ++j) {
        int r = blockIdx.y * 32 + threadIdx.y + j * 8;
        t[threadIdx.y + j * 8][threadIdx.x] = in[(size_t)r * C + c];
    }
    __syncthreads();
    const int rr = blockIdx.y * 32 + threadIdx.x;
#pragma unroll
    for (int j = 0; j < 4; ++j) {
        int cc = blockIdx.x * 32 + threadIdx.y + j * 8;
        outT[(size_t)cc * R + rr] = tf32rna(t[threadIdx.x][threadIdx.y + j * 8]);
    }
}

// ---------------------------------------------------------------------------
// bf16 GEMM tiling (unchanged proven path for qkv)
// ---------------------------------------------------------------------------
#define TSTRIDE 40
#define TILEB (128 * TSTRIDE * 2)
#define STAGEB (4 * TILEB)                  // 40960
#define GEMM_SMEM_BYTES (2 * STAGEB)        // 81920

__global__ void __launch_bounds__(512, 1) gemm_qkv(
    const __nv_bfloat16* __restrict__ Ahi, const __nv_bfloat16* __restrict__ Alo,
    const __nv_bfloat16* __restrict__ Bthi, const __nv_bfloat16* __restrict__ Btlo,
    __nv_bfloat16* __restrict__ qhi, __nv_bfloat16* __restrict__ qlo,
    __nv_bfloat16* __restrict__ khi, __nv_bfloat16* __restrict__ klo,
    __nv_bfloat16* __restrict__ vThi, __nv_bfloat16* __restrict__ vTlo)
{
    extern __shared__ char smem[];
    const uint32_t smb = smem_u32(smem);
    const int tid = threadIdx.x;
    const int lane = tid & 31;
    const int wid = tid >> 5;
    const int mw = wid >> 2;
    const int nw = wid & 3;
    const int K = DD;
    const int NT = (QKVC >> 7) * (MM >> 7);   // 768

    const int grow = tid >> 2;
    const int gcol = (tid & 3) << 3;
    const uint32_t stb = (uint32_t)(grow * TSTRIDE + gcol) * 2;

    uint32_t aoff[2];
#pragma unroll
    for (int mt = 0; mt < 2; ++mt)
        aoff[mt] = (uint32_t)((mw * 32 + mt * 16 + (lane & 15)) * TSTRIDE
                              + ((lane >> 4) << 3)) * 2;
    const int brow = nw * 32 + (lane & 7) + ((lane >> 4) << 3);
    const int bcol = ((lane >> 3) & 1) << 3;
    uint32_t boff[2];
    boff[0] = (uint32_t)(brow * TSTRIDE + bcol) * 2;
    boff[1] = (uint32_t)((brow + 16) * TSTRIDE + bcol) * 2;

    const int nst = K >> 5;

    for (int tile = blockIdx.x; tile < NT; tile += NSM) {
        const int m0 = (tile / 24) << 7;
        const int n0 = (tile % 24) << 7;
        const __nv_bfloat16* gAh = Ahi  + (size_t)(m0 + grow) * K + gcol;
        const __nv_bfloat16* gAl = Alo  + (size_t)(m0 + grow) * K + gcol;
        const __nv_bfloat16* gBh = Bthi + (size_t)(n0 + grow) * K + gcol;
        const __nv_bfloat16* gBl = Btlo + (size_t)(n0 + grow) * K + gcol;

        float acc[2][4][4];
#pragma unroll
        for (int i = 0; i < 2; ++i)
#pragma unroll
            for (int j = 0; j < 4; ++j)
#pragma unroll
                for (int k = 0; k < 4; ++k) acc[i][j][k] = 0.f;

        {
            const uint32_t d = smb + stb;
            CP16(d,             gAh);
            CP16(d + TILEB,     gAl);
            CP16(d + 2 * TILEB, gBh);
            CP16(d + 3 * TILEB, gBl);
            CP_COMMIT(); CP_WAIT0();
        }
        __syncthreads();

        for (int s = 0; s < nst; ++s) {
            if (s + 1 < nst) {
                const int k0 = (s + 1) << 5;
                const uint32_t d = smb + ((s + 1) & 1) * STAGEB + stb;
                CP16(d,             gAh + k0);
                CP16(d + TILEB,     gAl + k0);
                CP16(d + 2 * TILEB, gBh + k0);
                CP16(d + 3 * TILEB, gBl + k0);
                CP_COMMIT();
            }
            const uint32_t sb = smb + (s & 1) * STAGEB;
#pragma unroll
            for (int kk = 0; kk < 2; ++kk) {
                const uint32_t kb = kk * 32;
                uint32_t ah[2][4], al[2][4], bh[4][2], bl[4][2];
#pragma unroll
                for (int mt = 0; mt < 2; ++mt) {
                    LDSM4(ah[mt], sb + aoff[mt] + kb);
                    LDSM4(al[mt], sb + TILEB + aoff[mt] + kb);
                }
#pragma unroll
                for (int p = 0; p < 2; ++p) {
                    uint32_t t4[4];
                    LDSM4(t4, sb + 2 * TILEB + boff[p] + kb);
                    bh[2 * p][0] = t4[0]; bh[2 * p][1] = t4[1];
                    bh[2 * p + 1][0] = t4[2]; bh[2 * p + 1][1] = t4[3];
                    LDSM4(t4, sb + 3 * TILEB + boff[p] + kb);
                    bl[2 * p][0] = t4[0]; bl[2 * p][1] = t4[1];
                    bl[2 * p + 1][0] = t4[2]; bl[2 * p + 1][1] = t4[3];
                }
#pragma unroll
                for (int mt = 0; mt < 2; ++mt)
#pragma unroll
                    for (int nt = 0; nt < 4; ++nt)
                        MMA_BF16(acc[mt][nt], ah[mt], bh[nt]);
#pragma unroll
                for (int mt = 0; mt < 2; ++mt)
#pragma unroll
                    for (int nt = 0; nt < 4; ++nt)
                        MMA_BF16(acc[mt][nt], ah[mt], bl[nt]);
#pragma unroll
                for (int mt = 0; mt < 2; ++mt)
#pragma unroll
                    for (int nt = 0; nt < 4; ++nt)
                        MMA_BF16(acc[mt][nt], al[mt], bh[nt]);
            }
            CP_WAIT0();
            __syncthreads();
        }

#pragma unroll
        for (int nt = 0; nt < 4; ++nt) {
            const int cc = n0 + nw * 32 + nt * 8 + ((lane & 3) << 1);
            const int sec = cc >> 10;
            const int h = (cc & 1023) >> 6;
            const int d = cc & 63;
#pragma unroll
            for (int mt = 0; mt < 2; ++mt) {
                const int r0 = m0 + mw * 32 + mt * 16 + (lane >> 2);
                const int b = r0 >> 10;
                const int n = r0 & 1023;
                const size_t bhbase = ((size_t)b * HH + h);
                if (sec == 0) {
                    store_hilo2(qhi, qlo, (bhbase * NN + n) * DHH + d,
                                acc[mt][nt][0] * 0.125f, acc[mt][nt][1] * 0.125f);
                    store_hilo2(qhi, qlo, (bhbase * NN + n + 8) * DHH + d,
                                acc[mt][nt][2] * 0.125f, acc[mt][nt][3] * 0.125f);
                } else if (sec == 1) {
                    store_hilo2(khi, klo, (bhbase * NN + n) * DHH + d,
                                acc[mt][nt][0], acc[mt][nt][1]);
                    store_hilo2(khi, klo, (bhbase * NN + n + 8) * DHH + d,
                                acc[mt][nt][2], acc[mt][nt][3]);
                } else {
                    const size_t vb = bhbase * DHH;
                    store_hilo1(vThi, vTlo, (vb + d) * NN + n,         acc[mt][nt][0]);
                    store_hilo1(vThi, vTlo, (vb + d + 1) * NN + n,     acc[mt][nt][1]);
                    store_hilo1(vThi, vTlo, (vb + d) * NN + n + 8,     acc[mt][nt][2]);
                    store_hilo1(vThi, vTlo, (vb + d + 1) * NN + n + 8, acc[mt][nt][3]);
                }
            }
        }
    }
}

// ---------------------------------------------------------------------------
// tf32 out-projection GEMM: out = ao @ woT^T + bias. Single product, fp32 acc.
// 128x128 CTA tile, BK=32 floats, 16 warps 32x32, 2-stage, persistent.
// ---------------------------------------------------------------------------
#define TFSTR 36
#define TFTILEB (128 * TFSTR * 4)           // 18432
#define TFSTAGEB (2 * TFTILEB)              // 36864
#define TF_SMEM_BYTES (2 * TFSTAGEB)        // 73728

__global__ void __launch_bounds__(512, 1) gemm_out_tf32(
    const float* __restrict__ A, const float* __restrict__ Bt,
    const float* __restrict__ bias, float* __restrict__ C)
{
    extern __shared__ char smem[];
    const uint32_t smb = smem_u32(smem);
    const int tid = threadIdx.x;
    const int lane = tid & 31;
    const int wid = tid >> 5;
    const int mw = wid >> 2;
    const int nw = wid & 3;
    const int NT = (MM >> 7) * (INNERC >> 7);   // 32*8 = 256

    const int grow = tid >> 2;
    const int gcolf = (tid & 3) << 3;
    const uint32_t stb = (uint32_t)(grow * TFSTR + gcolf) * 4;

    const int mat = lane >> 3;
    const int rr = lane & 7;
    uint32_t aoff[2];
#pragma unroll
    for (int mt = 0; mt < 2; ++mt)
        aoff[mt] = (uint32_t)((mw * 32 + mt * 16 + ((mat & 1) << 3) + rr) * TFSTR
                              + ((mat >> 1) << 2)) * 4;
    uint32_t boff[2];
#pragma unroll
    for (int p = 0; p < 2; ++p)
        boff[p] = (uint32_t)((nw * 32 + p * 16 + ((mat >> 1) << 3) + rr) * TFSTR
                             + ((mat & 1) << 2)) * 4;

    const int nst = INNERC >> 5;   // 32

    for (int tile = blockIdx.x; tile < NT; tile += NSM) {
        const int m0 = (tile >> 3) << 7;
        const int n0 = (tile & 7) << 7;
        const float* gA = A  + (size_t)(m0 + grow) * INNERC + gcolf;
        const float* gB = Bt + (size_t)(n0 + grow) * INNERC + gcolf;

        float acc[2][4][4];
#pragma unroll
        for (int i = 0; i < 2; ++i)
#pragma unroll
            for (int j = 0; j < 4; ++j)
#pragma unroll
                for (int k = 0; k < 4; ++k) acc[i][j][k] = 0.f;

        {
            const uint32_t d = smb + stb;
            CP16(d,      gA); CP16(d + 16,      gA + 4);
            CP16(d + TFTILEB, gB); CP16(d + TFTILEB + 16, gB + 4);
            CP_COMMIT(); CP_WAIT0();
        }
        __syncthreads();

        for (int s = 0; s < nst; ++s) {
            if (s + 1 < nst) {
                const int k0 = (s + 1) << 5;
                const uint32_t d = smb + ((s + 1) & 1) * TFSTAGEB + stb;
                CP16(d,      gA + k0); CP16(d + 16,      gA + k0 + 4);
                CP16(d + TFTILEB, gB + k0); CP16(d + TFTILEB + 16, gB + k0 + 4);
                CP_COMMIT();
            }
            const uint32_t sb = smb + (s & 1) * TFSTAGEB;
#pragma unroll
            for (int kc = 0; kc < 4; ++kc) {
                const uint32_t kb = kc * 32;   // 8 floats
                uint32_t af[2][4], bf[4][2];
#pragma unroll
                for (int mt = 0; mt < 2; ++mt)
                    LDSM4(af[mt], sb + aoff[mt] + kb);
#pragma unroll
                for (int p = 0; p < 2; ++p) {
                    uint32_t t4[4];
                    LDSM4(t4, sb + TFTILEB + boff[p] + kb);
                    bf[2 * p][0] = t4[0]; bf[2 * p][1] = t4[1];
                    bf[2 * p + 1][0] = t4[2]; bf[2 * p + 1][1] = t4[3];
                }
#pragma unroll
                for (int mt = 0; mt < 2; ++mt)
#pragma unroll
                    for (int nt = 0; nt < 4; ++nt)
                        MMA_TF32(acc[mt][nt], af[mt], bf[nt]);
            }
            CP_WAIT0();
            __syncthreads();
        }

#pragma unroll
        for (int mt = 0; mt < 2; ++mt) {
            const int r0 = m0 + mw * 32 + mt * 16 + (lane >> 2);
#pragma unroll
            for (int nt = 0; nt < 4; ++nt) {
                const int cc = n0 + nw * 32 + nt * 8 + ((lane & 3) << 1);
                float2 bv = *(const float2*)(bias + cc);
                float2 v0 = make_float2(acc[mt][nt][0] + bv.x, acc[mt][nt][1] + bv.y);
                float2 v1 = make_float2(acc[mt][nt][2] + bv.x, acc[mt][nt][3] + bv.y);
                *(float2*)(C + (size_t)r0 * INNERC + cc) = v0;
                *(float2*)(C + (size_t)(r0 + 8) * INNERC + cc) = v1;
            }
        }
    }
}

// ---------------------------------------------------------------------------
// flash_tc: fused masked attention, 512 threads (8 row-groups x 2 col-halves),
// persistent over (bh, 128-row Q tile). Writes fp32 (tf32-rounded) ao.
// ---------------------------------------------------------------------------
#define FQSTR 72
#define FQTILE 18432                      // 128*72*2
#define FVSTR 136
#define FVTILE 17408                      // 64*136*2
#define F_MASK 0
#define F_RED  4096
#define F_RED2 5120
#define F_QHI  6144
#define F_QLO  (F_QHI + FQTILE)           // 24576
#define F_K(st) (43008 + (st) * 2 * FQTILE)
#define F_V(st) (116736 + (st) * 2 * FVTILE)
#define FLASH_SMEM 186368

__global__ void __launch_bounds__(512, 1) flash_tc(
    const __nv_bfloat16* __restrict__ qhi, const __nv_bfloat16* __restrict__ qlo,
    const __nv_bfloat16* __restrict__ khi, const __nv_bfloat16* __restrict__ klo,
    const __nv_bfloat16* __restrict__ vThi, const __nv_bfloat16* __restrict__ vTlo,
    const float* __restrict__ mask, float* __restrict__ ao)
{
    extern __shared__ char smem[];
    const uint32_t smb = smem_u32(smem);
    const int tid = threadIdx.x;
    const int lane = tid & 31;
    const int wid = tid >> 5;       // 0..15
    const int rg = wid >> 1;        // 0..7 row group
    const int ch = wid & 1;         // column half
    const int rw = rg * 16;
    const int rloc = lane >> 2;

    const uint32_t bkbase = (uint32_t)((ch * 64 + (lane & 7) + ((lane >> 4) << 3)) * FQSTR
                                       + (((lane >> 3) & 1) << 3)) * 2;
    const uint32_t bvbase = (uint32_t)(((lane & 7) + ((lane >> 4) << 3)) * FVSTR
                                       + (((lane >> 3) & 1) << 3)) * 2;
    const uint32_t aQ = (uint32_t)((rw + (lane & 15)) * FQSTR + ((lane >> 4) << 3)) * 2;
    const float* smask = (const float*)smem;
    float* redt = (float*)(smem + F_RED);
    float* reds = (float*)(smem + F_RED2);
    const int rbase = (rg * 8 + rloc) * 4;

    for (int tile = blockIdx.x; tile < 512; tile += NSM) {
        const int bh = tile >> 3;
        const int i0 = (tile & 7) << 7;
        const int b = bh >> 4;
        const int h = bh & 15;
        const size_t hb = (size_t)bh * NN * DHH;
        const __nv_bfloat16* kH = khi + hb;
        const __nv_bfloat16* kL = klo + hb;
        const __nv_bfloat16* vH = vThi + (size_t)bh * DHH * NN;
        const __nv_bfloat16* vL = vTlo + (size_t)bh * DHH * NN;

        // ---- prologue: mask + Q + K0 + V0
        if (tid < 256) CP16(smb + F_MASK + tid * 16, mask + b * NN + tid * 4);
#pragma unroll
        for (int t = 0; t < 2; ++t) {
            const int idx = tid + t * 512;
            const int row = idx >> 3;
            const int col = (idx & 7) << 3;
            const uint32_t so = (uint32_t)(row * FQSTR + col) * 2;
            CP16(smb + F_QHI + so, qhi + hb + (size_t)(i0 + row) * DHH + col);
            CP16(smb + F_QLO + so, qlo + hb + (size_t)(i0 + row) * DHH + col);
            CP16(smb + F_K(0) + so,          kH + (size_t)row * DHH + col);
            CP16(smb + F_K(0) + FQTILE + so, kL + (size_t)row * DHH + col);
        }
#pragma unroll
        for (int t = 0; t < 2; ++t) {
            const int idx = tid + t * 512;
            const int vr = idx >> 4;
            const int vc = (idx & 15) << 3;
            const uint32_t so = (uint32_t)(vr * FVSTR + vc) * 2;
            CP16(smb + F_V(0) + so,          vH + (size_t)vr * NN + vc);
            CP16(smb + F_V(0) + FVTILE + so, vL + (size_t)vr * NN + vc);
        }
        CP_COMMIT(); CP_WAIT0();
        __syncthreads();

        const float mi0 = mask[b * NN + i0 + rw + rloc];
        const float mi1 = mask[b * NN + i0 + rw + rloc + 8];
        const bool rv0 = (mi0 != 0.f);
        const bool rv1 = (mi1 != 0.f);
        float m0 = -1e30f, m1 = -1e30f, l0 = 0.f, l1 = 0.f;
        float oacc[8][4];
#pragma unroll
        for (int i = 0; i < 8; ++i)
#pragma unroll
            for (int j = 0; j < 4; ++j) oacc[i][j] = 0.f;

        for (int kt = 0; kt < 8; ++kt) {
            if (kt + 1 < 8) {
                const int st = (kt + 1) & 1;
                const int j0 = (kt + 1) * 128;
#pragma unroll
                for (int t = 0; t < 2; ++t) {
                    const int idx = tid + t * 512;
                    const int row = idx >> 3;
                    const int col = (idx & 7) << 3;
                    const uint32_t so = (uint32_t)(row * FQSTR + col) * 2;
                    CP16(smb + F_K(st) + so,          kH + (size_t)(j0 + row) * DHH + col);
                    CP16(smb + F_K(st) + FQTILE + so, kL + (size_t)(j0 + row) * DHH + col);
                }
#pragma unroll
                for (int t = 0; t < 2; ++t) {
                    const int idx = tid + t * 512;
                    const int vr = idx >> 4;
                    const int vc = (idx & 15) << 3;
                    const uint32_t so = (uint32_t)(vr * FVSTR + vc) * 2;
                    CP16(smb + F_V(st) + so,          vH + (size_t)vr * NN + j0 + vc);
                    CP16(smb + F_V(st) + FVTILE + so, vL + (size_t)vr * NN + j0 + vc);
                }
                CP_COMMIT();
            }

            const uint32_t kbh = smb + F_K(kt & 1);
            const uint32_t kbl = kbh + FQTILE;
            const uint32_t vbh = smb + F_V(kt & 1);
            const uint32_t vbl = vbh + FVTILE;

            // ---- S (this warp: 16 rows x 64 cols of the score tile)
            float sacc[8][4];
#pragma unroll
            for (int i = 0; i < 8; ++i)
#pragma unroll
                for (int j = 0; j < 4; ++j) sacc[i][j] = 0.f;
#pragma unroll
            for (int kk = 0; kk < 4; ++kk) {
                const uint32_t kb = kk * 32;
                uint32_t qh4[4], ql4[4];
                LDSM4(qh4, smb + F_QHI + aQ + kb);
                LDSM4(ql4, smb + F_QLO + aQ + kb);
#pragma unroll
                for (int p = 0; p < 4; ++p) {
                    uint32_t tbh[4], tbl[4];
                    LDSM4(tbh, kbh + bkbase + p * 2304 + kb);
                    LDSM4(tbl, kbl + bkbase + p * 2304 + kb);
                    MMA_BF16(sacc[2 * p],     qh4, tbh);
                    MMA_BF16(sacc[2 * p + 1], qh4, tbh + 2);
                    MMA_BF16(sacc[2 * p],     qh4, tbl);
                    MMA_BF16(sacc[2 * p + 1], qh4, tbl + 2);
                    MMA_BF16(sacc[2 * p],     ql4, tbh);
                    MMA_BF16(sacc[2 * p + 1], ql4, tbh + 2);
                }
            }

            // ---- masked partial max over this half
            const int colbase = kt * 128 + ch * 64;
            float tmax0 = -1e30f, tmax1 = -1e30f;
#pragma unroll
            for (int nt = 0; nt < 8; ++nt) {
                const float2 mv = *(const float2*)(smask + colbase + nt * 8 + ((lane & 3) << 1));
                const bool g0 = (mv.x != 0.f);
                const bool g1 = (mv.y != 0.f);
                float s0 = (rv0 && g0) ? sacc[nt][0] : -1e30f;
                float s1 = (rv0 && g1) ? sacc[nt][1] : -1e30f;
                float s2 = (rv1 && g0) ? sacc[nt][2] : -1e30f;
                float s3 = (rv1 && g1) ? sacc[nt][3] : -1e30f;
                sacc[nt][0] = s0; sacc[nt][1] = s1; sacc[nt][2] = s2; sacc[nt][3] = s3;
                tmax0 = fmaxf(tmax0, fmaxf(s0, s1));
                tmax1 = fmaxf(tmax1, fmaxf(s2, s3));
            }
            tmax0 = fmaxf(tmax0, __shfl_xor_sync(0xffffffffu, tmax0, 1));
            tmax0 = fmaxf(tmax0, __shfl_xor_sync(0xffffffffu, tmax0, 2));
            tmax1 = fmaxf(tmax1, __shfl_xor_sync(0xffffffffu, tmax1, 1));
            tmax1 = fmaxf(tmax1, __shfl_xor_sync(0xffffffffu, tmax1, 2));
            // exchange partial max with partner column-half
            if ((lane & 3) == 0) { redt[rbase + ch] = tmax0; redt[rbase + 2 + ch] = tmax1; }
            __syncthreads();
            tmax0 = fmaxf(tmax0, redt[rbase + (ch ^ 1)]);
            tmax1 = fmaxf(tmax1, redt[rbase + 2 + (ch ^ 1)]);

            const float mn0 = fmaxf(m0, tmax0);
            const float mn1 = fmaxf(m1, tmax1);
            const float sc0 = __expf(m0 - mn0);
            const float sc1 = __expf(m1 - mn1);
            m0 = mn0; m1 = mn1;

            float ls0 = 0.f, ls1 = 0.f;
#pragma unroll
            for (int nt = 0; nt < 8; ++nt) {
                float e0 = (sacc[nt][0] > -1e29f) ? __expf(sacc[nt][0] - mn0) : 0.f;
                float e1 = (sacc[nt][1] > -1e29f) ? __expf(sacc[nt][1] - mn0) : 0.f;
                float e2 = (sacc[nt][2] > -1e29f) ? __expf(sacc[nt][2] - mn1) : 0.f;
                float e3 = (sacc[nt][3] > -1e29f) ? __expf(sacc[nt][3] - mn1) : 0.f;
                sacc[nt][0] = e0; sacc[nt][1] = e1; sacc[nt][2] = e2; sacc[nt][3] = e3;
                ls0 += e0 + e1; ls1 += e2 + e3;
            }
            ls0 += __shfl_xor_sync(0xffffffffu, ls0, 1);
            ls0 += __shfl_xor_sync(0xffffffffu, ls0, 2);
            ls1 += __shfl_xor_sync(0xffffffffu, ls1, 1);
            ls1 += __shfl_xor_sync(0xffffffffu, ls1, 2);
            // exchange partial sums
            if ((lane & 3) == 0) { reds[rbase + ch] = ls0; reds[rbase + 2 + ch] = ls1; }
            __syncthreads();
            ls0 += reds[rbase + (ch ^ 1)];
            ls1 += reds[rbase + 2 + (ch ^ 1)];
            l0 = l0 * sc0 + ls0;
            l1 = l1 * sc1 + ls1;
#pragma unroll
            for (int no = 0; no < 8; ++no) {
                oacc[no][0] *= sc0; oacc[no][1] *= sc0;
                oacc[no][2] *= sc1; oacc[no][3] *= sc1;
            }

            // ---- partial O += P @ V over this half's j range
#pragma unroll
            for (int kc = 0; kc < 4; ++kc) {
                uint32_t pah[4], pal[4];
                cvt_hilo(sacc[2 * kc][0],     sacc[2 * kc][1],     pah[0], pal[0]);
                cvt_hilo(sacc[2 * kc][2],     sacc[2 * kc][3],     pah[1], pal[1]);
                cvt_hilo(sacc[2 * kc + 1][0], sacc[2 * kc + 1][1], pah[2], pal[2]);
                cvt_hilo(sacc[2 * kc + 1][2], sacc[2 * kc + 1][3], pah[3], pal[3]);
                const uint32_t jo = ch * 128 + kc * 32;
#pragma unroll
                for (int dv = 0; dv < 4; ++dv) {
                    uint32_t vb[4], vl[4];
                    LDSM4(vb, vbh + bvbase + dv * 4352 + jo);
                    LDSM4(vl, vbl + bvbase + dv * 4352 + jo);
                    MMA_BF16(oacc[2 * dv],     pah, vb);
                    MMA_BF16(oacc[2 * dv + 1], pah, vb + 2);
                    MMA_BF16(oacc[2 * dv],     pah, vl);
                    MMA_BF16(oacc[2 * dv + 1], pah, vl + 2);
                    MMA_BF16(oacc[2 * dv],     pal, vb);
                    MMA_BF16(oacc[2 * dv + 1], pal, vb + 2);
                }
            }
            CP_WAIT0();
            __syncthreads();
        }

        // ---- combine partner halves and store (fp32 tf32-rounded)
        float* cmb = (float*)(smem + F_K(0));
        const float inv0 = (l0 > 0.f) ? 1.f / l0 : 0.f;
        const float inv1 = (l1 > 0.f) ? 1.f / l1 : 0.f;
        if (ch == 0) {
#pragma unroll
            for (int no = 0; no < 8; ++no) {
                const int col = no * 8 + ((lane & 3) << 1);
                cmb[(rw + rloc) * 65 + col]         = oacc[no][0];
                cmb[(rw + rloc) * 65 + col + 1]     = oacc[no][1];
                cmb[(rw + rloc + 8) * 65 + col]     = oacc[no][2];
                cmb[(rw + rloc + 8) * 65 + col + 1] = oacc[no][3];
            }
        }
        __syncthreads();
        if (ch == 1) {
            const int r0g = i0 + rw + rloc;
#pragma unroll
            for (int no = 0; no < 8; ++no) {
                const int col = no * 8 + ((lane & 3) << 1);
                const float v00 = (cmb[(rw + rloc) * 65 + col]         + oacc[no][0]) * inv0;
                const float v01 = (cmb[(rw + rloc) * 65 + col + 1]     + oacc[no][1]) * inv0;
                const float v10 = (cmb[(rw + rloc + 8) * 65 + col]     + oacc[no][2]) * inv1;
                const float v11 = (cmb[(rw + rloc + 8) * 65 + col + 1] + oacc[no][3]) * inv1;
                const size_t c = (size_t)h * 64 + col;
                ao[((size_t)b * NN + r0g) * INNERC + c]         = tf32rna(v00);
                ao[((size_t)b * NN + r0g) * INNERC + c + 1]     = tf32rna(v01);
                ao[((size_t)b * NN + r0g + 8) * INNERC + c]     = tf32rna(v10);
                ao[((size_t)b * NN + r0g + 8) * INNERC + c + 1] = tf32rna(v11);
            }
        }
        __syncthreads();
    }
}

// ---------------------------------------------------------------------------
extern "C" void kernel_launch(void* const* d_in, const int* in_sizes, int n_in,
                              void* d_out, int out_size)
{
    const float* x      = (const float*)d_in[0];
    const float* mask   = (const float*)d_in[1];
    const float* w_qkv  = (const float*)d_in[2];
    const float* w_out  = (const float*)d_in[3];
    const float* b_out  = (const float*)d_in[4];
    float* out = (float*)d_out;

    __nv_bfloat16 *xhi, *xlo, *wqhi, *wqlo;
    __nv_bfloat16 *qhi, *qlo, *khi, *klo, *vThi, *vTlo;
    float *woT, *ao;
    cudaGetSymbolAddress((void**)&xhi, g_xhi);
    cudaGetSymbolAddress((void**)&xlo, g_xlo);
    cudaGetSymbolAddress((void**)&wqhi, g_wqkvThi);
    cudaGetSymbolAddress((void**)&wqlo, g_wqkvTlo);
    cudaGetSymbolAddress((void**)&woT, g_woT);
    cudaGetSymbolAddress((void**)&ao, g_ao);
    cudaGetSymbolAddress((void**)&qhi, g_qhi);
    cudaGetSymbolAddress((void**)&qlo, g_qlo);
    cudaGetSymbolAddress((void**)&khi, g_khi);
    cudaGetSymbolAddress((void**)&klo, g_klo);
    cudaGetSymbolAddress((void**)&vThi, g_vThi);
    cudaGetSymbolAddress((void**)&vTlo, g_vTlo);

    cudaFuncSetAttribute(gemm_qkv, cudaFuncAttributeMaxDynamicSharedMemorySize,
                         GEMM_SMEM_BYTES);
    cudaFuncSetAttribute(gemm_out_tf32, cudaFuncAttributeMaxDynamicSharedMemorySize,
                         TF_SMEM_BYTES);
    cudaFuncSetAttribute(flash_tc, cudaFuncAttributeMaxDynamicSharedMemorySize,
                         FLASH_SMEM);

    // 0) prep
    split_kernel<<<(MM * DD / 4 + 255) / 256, 256>>>(x, xhi, xlo, MM * DD / 4);
    splitT_kernel<<<dim3(QKVC / 32, DD / 32), dim3(32, 8)>>>(w_qkv, wqhi, wqlo, DD, QKVC);
    transT_rna<<<dim3(INNERC / 32, INNERC / 32), dim3(32, 8)>>>(w_out, woT,
                                                                INNERC, INNERC);
    // 1) qkv projection (persistent bf16-3) -> q(*0.125)/k hi/lo + v transposed
    gemm_qkv<<<NSM, 512, GEMM_SMEM_BYTES>>>(
        xhi, xlo, wqhi, wqlo, qhi, qlo, khi, klo, vThi, vTlo);
    // 2) fused masked flash attention (persistent, 512 thr) -> ao fp32(tf32)
    flash_tc<<<NSM, 512, FLASH_SMEM>>>(
        qhi, qlo, khi, klo, vThi, vTlo, mask, ao);
    // 3) out projection (persistent tf32 single-product)
    gemm_out_tf32<<<NSM, 512, TF_SMEM_BYTES>>>(ao, woT, b_out, out);
}